// round 12
// baseline (speedup 1.0000x reference)
#include <cuda_runtime.h>
#include <cuda_bf16.h>
#include <math.h>

#define NH    8
#define EDIM  32
#define WS    8
#define MO    12
#define NKEY  (MO*MO)      // 144
#define BATCH 16
#define CCH   256
#define HH    64
#define WW    64
#define PIX   (HH*WW)      // 4096
#define NWIN  8

typedef unsigned long long u64;
typedef unsigned int u32;

// Scratch buffers
__device__ float g_Q[BATCH * NH * PIX * EDIM];    // (b, head, pixel, e)
__device__ float g_K[BATCH * NH * PIX * EDIM];
__device__ float g_V[BATCH * NH * PIX * EDIM];

// bf16 hi/lo split scratch
__device__ __nv_bfloat16 g_xh[BATCH * PIX * CCH];   // x transposed: (b, p, c)
__device__ __nv_bfloat16 g_xl[BATCH * PIX * CCH];
__device__ __nv_bfloat16 g_w1h[768 * CCH];          // (n, k)
__device__ __nv_bfloat16 g_w1l[768 * CCH];
__device__ __nv_bfloat16 g_w2h[CCH * CCH];
__device__ __nv_bfloat16 g_w2l[CCH * CCH];
__device__ __nv_bfloat16 g_atth[BATCH * PIX * CCH]; // attn out hi (b, p, c)
__device__ __nv_bfloat16 g_attl[BATCH * PIX * CCH]; // attn out lo

// ---- fast exp on FMA pipe ----
__device__ __forceinline__ float fast_exp(float x) {
    float y = fmaxf(x * 1.4426950408889634f, -125.0f);
    float z = y + 12582912.0f;
    int   n = __float_as_int(z) - 0x4B400000;
    float f = y - (z - 12582912.0f);
    float p = 1.540353039338161e-4f;
    p = fmaf(p, f, 0.0013333558146428443f);
    p = fmaf(p, f, 0.009618129107628477f);
    p = fmaf(p, f, 0.05550410866482158f);
    p = fmaf(p, f, 0.2402265069591007f);
    p = fmaf(p, f, 0.6931471805599453f);
    p = fmaf(p, f, 1.0f);
    return p * __int_as_float((n + 127) << 23);
}

// ---- mma.sync helpers ----
__device__ __forceinline__ u32 smem_u32(const void* p) {
    u32 a; asm("{ .reg .u64 t; cvta.to.shared.u64 t, %1; cvt.u32.u64 %0, t; }"
               : "=r"(a) : "l"(p));
    return a;
}
__device__ __forceinline__ void ldsm4(u32* r, u32 addr) {
    asm volatile("ldmatrix.sync.aligned.m8n8.x4.shared.b16 {%0,%1,%2,%3}, [%4];"
                 : "=r"(r[0]), "=r"(r[1]), "=r"(r[2]), "=r"(r[3]) : "r"(addr));
}
__device__ __forceinline__ void ldsm4t(u32* r, u32 addr) {
    asm volatile("ldmatrix.sync.aligned.m8n8.x4.trans.shared.b16 {%0,%1,%2,%3}, [%4];"
                 : "=r"(r[0]), "=r"(r[1]), "=r"(r[2]), "=r"(r[3]) : "r"(addr));
}
__device__ __forceinline__ void mma_bf16(float* d, const u32* a, const u32* b) {
    asm volatile(
        "mma.sync.aligned.m16n8k16.row.col.f32.bf16.bf16.f32 "
        "{%0,%1,%2,%3}, {%4,%5,%6,%7}, {%8,%9}, {%0,%1,%2,%3};"
        : "+f"(d[0]), "+f"(d[1]), "+f"(d[2]), "+f"(d[3])
        : "r"(a[0]), "r"(a[1]), "r"(a[2]), "r"(a[3]), "r"(b[0]), "r"(b[1]));
}
__device__ __forceinline__ void cp16(u32 dst, const void* src) {
    asm volatile("cp.async.cg.shared.global [%0], [%1], 16;"
                 :: "r"(dst), "l"(src));
}
#define CP_COMMIT() asm volatile("cp.async.commit_group;" ::: "memory")
#define CP_WAIT0()  asm volatile("cp.async.wait_group 0;" ::: "memory")
#define CP_WAIT1()  asm volatile("cp.async.wait_group 1;" ::: "memory")

__device__ __forceinline__ void split_bf16(float v, __nv_bfloat16& hi, __nv_bfloat16& lo) {
    hi = __float2bfloat16(v);
    lo = __float2bfloat16(v - __bfloat162float(hi));
}
// pack two fp32 -> bf16x2 register
__device__ __forceinline__ u32 pkbf2(float lo, float hi) {
    u32 d; asm("cvt.rn.bf16x2.f32 %0, %1, %2;" : "=r"(d) : "f"(hi), "f"(lo));
    return d;
}
__device__ __forceinline__ void split4(float4 v, uint2& hi, uint2& lo) {
    hi.x = pkbf2(v.x, v.y);
    hi.y = pkbf2(v.z, v.w);
    __nv_bfloat162 h0 = *(__nv_bfloat162*)&hi.x;
    __nv_bfloat162 h1 = *(__nv_bfloat162*)&hi.y;
    lo.x = pkbf2(v.x - __bfloat162float(h0.x), v.y - __bfloat162float(h0.y));
    lo.y = pkbf2(v.z - __bfloat162float(h1.x), v.w - __bfloat162float(h1.y));
}

// Pipelined GEMM smem: K chunks of 32, 2 stages
#define KC     32
#define KCPAD  40                      // row stride (elements); 80 B
#define STAGE_B (128 * KCPAD * 2)      // 10240 bytes per array
#define STG4    (4 * STAGE_B)          // 40960 per stage (Ah, Al, Bh, Bl)
#define GEMM_SMEM (2 * STG4)           // 81920
#define NCHUNK (CCH / KC)              // 8

// ---------------------------------------------------------------------------
// Conversion kernels
// ---------------------------------------------------------------------------
__global__ void conv_x(const float* __restrict__ x) {
    __shared__ float tile[32][33];
    const int b  = blockIdx.z;
    const int p0 = blockIdx.x * 32;
    const int c0 = blockIdx.y * 32;
    const int tx = threadIdx.x, ty = threadIdx.y;   // 32 x 8
    const float* xb = x + ((size_t)b * CCH + c0) * PIX + p0;
#pragma unroll
    for (int i = 0; i < 32; i += 8)
        tile[ty + i][tx] = xb[(size_t)(ty + i) * PIX + tx];
    __syncthreads();
#pragma unroll
    for (int i = 0; i < 32; i += 8) {
        int p = p0 + ty + i;
        float v = tile[tx][ty + i];
        __nv_bfloat16 hi, lo; split_bf16(v, hi, lo);
        size_t o = ((size_t)b * PIX + p) * CCH + c0 + tx;
        g_xh[o] = hi;
        g_xl[o] = lo;
    }
}

__global__ void conv_w(const float* __restrict__ w, __nv_bfloat16* __restrict__ wh,
                       __nv_bfloat16* __restrict__ wl, int n) {
    int i = blockIdx.x * 256 + threadIdx.x;
    if (i < n) {
        __nv_bfloat16 hi, lo; split_bf16(w[i], hi, lo);
        wh[i] = hi;
        wl[i] = lo;
    }
}

// ---------------------------------------------------------------------------
// Kernel 1: QKV projection. Pipelined mma.sync bf16x3, 2-stage cp.async,
// 2 CTAs/SM.
// ---------------------------------------------------------------------------
__global__ __launch_bounds__(256, 2) void qkv_mma(const float* __restrict__ b1) {
    extern __shared__ char smem[];
    const u32 sb0 = smem_u32(smem);

    const int tid = threadIdx.x;
    const int lane = tid & 31, wid = tid >> 5;
    const int warp_m = wid >> 1, warp_n = wid & 1;
    const int b  = blockIdx.z;
    const int p0 = blockIdx.x * 128;
    const int n0 = blockIdx.y * 128;

    const int g = lane >> 3, rr = lane & 7;
    const u32 offA = (u32)(((warp_m * 32 + rr + (g & 1) * 8) * KCPAD + (g >> 1) * 8) * 2);
    const u32 offB = (u32)(((warp_n * 64 + (g >> 1) * 8 + rr) * KCPAD + (g & 1) * 8) * 2);

    float acc[2][8][4];
#pragma unroll
    for (int ma = 0; ma < 2; ma++)
#pragma unroll
        for (int na = 0; na < 8; na++)
#pragma unroll
            for (int v = 0; v < 4; v++) acc[ma][na][v] = 0.f;

    const __nv_bfloat16* Ah = g_xh + (size_t)b * PIX * CCH;
    const __nv_bfloat16* Al = g_xl + (size_t)b * PIX * CCH;

    auto issue = [&](int c, int s) {
        const int c0 = c * KC;
        const u32 ub = sb0 + s * STG4;
#pragma unroll
        for (int t = 0; t < 2; t++) {
            int idx = tid + t * 256;          // 0..511
            int row = idx >> 2, seg = idx & 3;
            size_t srcA = ((size_t)(p0 + row)) * CCH + c0 + seg * 8;
            size_t srcB = ((size_t)(n0 + row)) * CCH + c0 + seg * 8;
            u32 doff = (u32)(row * (KCPAD * 2) + seg * 16);
            cp16(ub + doff, Ah + srcA);
            cp16(ub + STAGE_B + doff, Al + srcA);
            cp16(ub + 2 * STAGE_B + doff, g_w1h + srcB);
            cp16(ub + 3 * STAGE_B + doff, g_w1l + srcB);
        }
        CP_COMMIT();
    };

    issue(0, 0);
#pragma unroll 1
    for (int c = 0; c < NCHUNK; c++) {
        const int s = c & 1;
        if (c + 1 < NCHUNK) { issue(c + 1, s ^ 1); CP_WAIT1(); }
        else                { CP_WAIT0(); }
        __syncthreads();

        const u32 uAh = sb0 + s * STG4;
        const u32 uAl = uAh + STAGE_B;
        const u32 uBh = uAh + 2 * STAGE_B;
        const u32 uBl = uAh + 3 * STAGE_B;
#pragma unroll
        for (int ks = 0; ks < 2; ks++) {
            const u32 ko = ks * 32;
            u32 ah[2][4], al[2][4];
            ldsm4(ah[0], uAh + offA + ko);
            ldsm4(ah[1], uAh + offA + ko + 16 * KCPAD * 2);
            ldsm4(al[0], uAl + offA + ko);
            ldsm4(al[1], uAl + offA + ko + 16 * KCPAD * 2);
#pragma unroll
            for (int ng = 0; ng < 4; ng++) {
                u32 bh[4], bl[4];
                ldsm4(bh, uBh + offB + ko + ng * (16 * KCPAD * 2));
                ldsm4(bl, uBl + offB + ko + ng * (16 * KCPAD * 2));
#pragma unroll
                for (int h = 0; h < 2; h++) {
                    const u32* bhf = bh + 2 * h;
                    const u32* blf = bl + 2 * h;
                    int na = ng * 2 + h;
#pragma unroll
                    for (int ma = 0; ma < 2; ma++) {
                        mma_bf16(acc[ma][na], ah[ma], bhf);
                        mma_bf16(acc[ma][na], ah[ma], blf);
                        mma_bf16(acc[ma][na], al[ma], bhf);
                    }
                }
            }
        }
        __syncthreads();
    }

    // Epilogue: scatter fp32 into Q/K/V
    const int r = lane >> 2;
    const int cp = (lane & 3) * 2;
#pragma unroll
    for (int ma = 0; ma < 2; ma++) {
#pragma unroll
        for (int na = 0; na < 8; na++) {
#pragma unroll
            for (int v = 0; v < 4; v++) {
                int m  = p0 + warp_m * 32 + ma * 16 + r + (v >> 1) * 8;
                int oc = n0 + warp_n * 64 + na * 8 + cp + (v & 1);
                float val = acc[ma][na][v] + b1[oc];
                int type = oc % 3;
                int ch   = oc / 3;
                int head = ch >> 5;
                int e    = ch & 31;
                float* dst = (type == 0) ? g_Q : (type == 1) ? g_K : g_V;
                dst[((size_t)(b * NH + head) * PIX + m) * EDIM + e] = val;
            }
        }
    }
}

// ---------------------------------------------------------------------------
// Kernel 2: windowed attention, mma.sync bf16x3, register-resident P.
// Unchanged from R11 (passing, ~150us).
// ---------------------------------------------------------------------------
#define EPAD 40              // e-stride (elements); row = 80 B
#define A_QH  0
#define A_QL  5120
#define A_KH  10240
#define A_KL  21760
#define A_VH  33280
#define A_VL  44800
#define ATTN_SMEM 56320

__global__ __launch_bounds__(128) void attn_mma() {
    extern __shared__ char sm[];
    const u32 sb = smem_u32(sm);

    const int b    = blockIdx.z;
    const int head = blockIdx.y;
    const int wi   = blockIdx.x >> 3;
    const int wj   = blockIdx.x & 7;
    const int tid  = threadIdx.x;
    const int lane = tid & 31;
    const int warp = tid >> 5;

    const size_t hb = (size_t)(b * NH + head) * PIX * EDIM;
    const float* Qg = g_Q + hb;
    const float* Kg = g_K + hb;
    const float* Vg = g_V + hb;
    const float scale = 0.17677669529663687f;   // 1/sqrt(32), folded into Q

    for (int idx = tid; idx < 64 * 8; idx += 128) {
        int q = idx >> 3, e4 = (idx & 7) * 4;
        int r = wi * 8 + (q >> 3);
        int c = wj * 8 + (q & 7);
        float4 v = *(const float4*)(Qg + (size_t)(r * WW + c) * EDIM + e4);
        v.x *= scale; v.y *= scale; v.z *= scale; v.w *= scale;
        uint2 hi, lo; split4(v, hi, lo);
        u32 doff = (u32)((q * EPAD + e4) * 2);
        *(uint2*)(sm + A_QH + doff) = hi;
        *(uint2*)(sm + A_QL + doff) = lo;
    }
    for (int idx = tid; idx < NKEY * 8; idx += 128) {
        int k = idx >> 3, e4 = (idx & 7) * 4;
        int kr = k / MO, kc = k % MO;
        int r = wi * 8 - 2 + kr;
        int c = wj * 8 - 2 + kc;
        float4 kv = make_float4(0.f, 0.f, 0.f, 0.f);
        float4 vv = kv;
        if (r >= 0 && r < HH && c >= 0 && c < WW) {
            size_t off = (size_t)(r * WW + c) * EDIM + e4;
            kv = *(const float4*)(Kg + off);
            vv = *(const float4*)(Vg + off);
        }
        uint2 khi, klo, vhi, vlo;
        split4(kv, khi, klo);
        split4(vv, vhi, vlo);
        u32 doff = (u32)((k * EPAD + e4) * 2);
        *(uint2*)(sm + A_KH + doff) = khi;
        *(uint2*)(sm + A_KL + doff) = klo;
        *(uint2*)(sm + A_VH + doff) = vhi;
        *(uint2*)(sm + A_VL + doff) = vlo;
    }
    __syncthreads();

    const int g = lane >> 3, rr = lane & 7;

    float acc[18][4];
#pragma unroll
    for (int na = 0; na < 18; na++)
#pragma unroll
        for (int v = 0; v < 4; v++) acc[na][v] = 0.f;
    {
        const u32 aoff = (u32)(((warp * 16 + rr + (g & 1) * 8) * EPAD + (g >> 1) * 8) * 2);
        const u32 boff = (u32)((((g >> 1) * 8 + rr) * EPAD + (g & 1) * 8) * 2);
#pragma unroll
        for (int ks = 0; ks < 2; ks++) {
            const u32 ko = ks * 32;
            u32 ah[4], al[4];
            ldsm4(ah, sb + A_QH + aoff + ko);
            ldsm4(al, sb + A_QL + aoff + ko);
#pragma unroll
            for (int ng = 0; ng < 9; ng++) {
                u32 bh[4], bl[4];
                const u32 nb = ng * (16 * EPAD * 2);
                ldsm4(bh, sb + A_KH + boff + nb + ko);
                ldsm4(bl, sb + A_KL + boff + nb + ko);
#pragma unroll
                for (int h = 0; h < 2; h++) {
                    int na = ng * 2 + h;
                    mma_bf16(acc[na], ah, bh + 2 * h);
                    mma_bf16(acc[na], ah, bl + 2 * h);
                    mma_bf16(acc[na], al, bh + 2 * h);
                }
            }
        }
    }

    {
        float m0 = -1e30f, m1 = -1e30f;
#pragma unroll
        for (int na = 0; na < 18; na++) {
            m0 = fmaxf(m0, fmaxf(acc[na][0], acc[na][1]));
            m1 = fmaxf(m1, fmaxf(acc[na][2], acc[na][3]));
        }
        m0 = fmaxf(m0, __shfl_xor_sync(0xFFFFFFFFu, m0, 1));
        m0 = fmaxf(m0, __shfl_xor_sync(0xFFFFFFFFu, m0, 2));
        m1 = fmaxf(m1, __shfl_xor_sync(0xFFFFFFFFu, m1, 1));
        m1 = fmaxf(m1, __shfl_xor_sync(0xFFFFFFFFu, m1, 2));
        float s0 = 0.f, s1 = 0.f;
#pragma unroll
        for (int na = 0; na < 18; na++) {
            acc[na][0] = fast_exp(acc[na][0] - m0);
            acc[na][1] = fast_exp(acc[na][1] - m0);
            acc[na][2] = fast_exp(acc[na][2] - m1);
            acc[na][3] = fast_exp(acc[na][3] - m1);
            s0 += acc[na][0] + acc[na][1];
            s1 += acc[na][2] + acc[na][3];
        }
        s0 += __shfl_xor_sync(0xFFFFFFFFu, s0, 1);
        s0 += __shfl_xor_sync(0xFFFFFFFFu, s0, 2);
        s1 += __shfl_xor_sync(0xFFFFFFFFu, s1, 1);
        s1 += __shfl_xor_sync(0xFFFFFFFFu, s1, 2);
        float i0 = 1.f / s0, i1 = 1.f / s1;
#pragma unroll
        for (int na = 0; na < 18; na++) {
            acc[na][0] *= i0;
            acc[na][1] *= i0;
            acc[na][2] *= i1;
            acc[na][3] *= i1;
        }
    }

    {
        float av[4][4];
#pragma unroll
        for (int na = 0; na < 4; na++)
#pragma unroll
            for (int v = 0; v < 4; v++) av[na][v] = 0.f;

        const u32 vrow = (u32)(((g & 1) * 8 + rr) * EPAD + (g >> 1) * 8);
#pragma unroll
        for (int ks = 0; ks < 9; ks++) {
            u32 ph[4], pl[4];
            {
                float c00 = acc[2 * ks][0],     c01 = acc[2 * ks][1];
                float c02 = acc[2 * ks][2],     c03 = acc[2 * ks][3];
                float c10 = acc[2 * ks + 1][0], c11 = acc[2 * ks + 1][1];
                float c12 = acc[2 * ks + 1][2], c13 = acc[2 * ks + 1][3];
                ph[0] = pkbf2(c00, c01);
                ph[1] = pkbf2(c02, c03);
                ph[2] = pkbf2(c10, c11);
                ph[3] = pkbf2(c12, c13);
                __nv_bfloat162 h0 = *(__nv_bfloat162*)&ph[0];
                __nv_bfloat162 h1 = *(__nv_bfloat162*)&ph[1];
                __nv_bfloat162 h2 = *(__nv_bfloat162*)&ph[2];
                __nv_bfloat162 h3 = *(__nv_bfloat162*)&ph[3];
                pl[0] = pkbf2(c00 - __bfloat162float(h0.x), c01 - __bfloat162float(h0.y));
                pl[1] = pkbf2(c02 - __bfloat162float(h1.x), c03 - __bfloat162float(h1.y));
                pl[2] = pkbf2(c10 - __bfloat162float(h2.x), c11 - __bfloat162float(h2.y));
                pl[3] = pkbf2(c12 - __bfloat162float(h3.x), c13 - __bfloat162float(h3.y));
            }
            const u32 kb = (u32)(ks * 16 * EPAD * 2);
#pragma unroll
            for (int half = 0; half < 2; half++) {
                u32 vh[4], vl[4];
                const u32 addr = kb + (vrow + half * 16) * 2;
                ldsm4t(vh, sb + A_VH + addr);
                ldsm4t(vl, sb + A_VL + addr);
#pragma unroll
                for (int h = 0; h < 2; h++) {
                    int na = half * 2 + h;
                    mma_bf16(av[na], ph, vh + 2 * h);
                    mma_bf16(av[na], ph, vl + 2 * h);
                    mma_bf16(av[na], pl, vh + 2 * h);
                }
            }
        }

        const int r0 = lane >> 2;
        const int e0 = (lane & 3) * 2;
#pragma unroll
        for (int half = 0; half < 2; half++) {
            int q = warp * 16 + r0 + half * 8;
            int r = wi * 8 + (q >> 3);
            int c = wj * 8 + (q & 7);
            size_t base = ((size_t)b * PIX + r * WW + c) * CCH + head * EDIM;
#pragma unroll
            for (int na = 0; na < 4; na++) {
                int e = na * 8 + e0;
                float o0 = av[na][half * 2 + 0];
                float o1 = av[na][half * 2 + 1];
                u32 hh = pkbf2(o0, o1);
                __nv_bfloat162 hv = *(__nv_bfloat162*)&hh;
                u32 ll = pkbf2(o0 - __bfloat162float(hv.x),
                               o1 - __bfloat162float(hv.y));
                *(u32*)((char*)(g_atth + base + e)) = hh;
                *(u32*)((char*)(g_attl + base + e)) = ll;
            }
        }
    }
}

// ---------------------------------------------------------------------------
// Kernel 3: output projection. Pipelined like qkv_mma.
// ---------------------------------------------------------------------------
__global__ __launch_bounds__(256, 2) void proj_mma(const float* __restrict__ b2,
                                                   float* __restrict__ y) {
    extern __shared__ char smem[];
    const u32 sb0 = smem_u32(smem);

    const int tid = threadIdx.x;
    const int lane = tid & 31, wid = tid >> 5;
    const int warp_m = wid >> 1, warp_n = wid & 1;
    const int b  = blockIdx.z;
    const int p0 = blockIdx.x * 128;
    const int n0 = blockIdx.y * 128;

    const int g = lane >> 3, rr = lane & 7;
    const u32 offA = (u32)(((warp_m * 32 + rr + (g & 1) * 8) * KCPAD + (g >> 1) * 8) * 2);
    const u32 offB = (u32)(((warp_n * 64 + (g >> 1) * 8 + rr) * KCPAD + (g & 1) * 8) * 2);

    float acc[2][8][4];
#pragma unroll
    for (int ma = 0; ma < 2; ma++)
#pragma unroll
        for (int na = 0; na < 8; na++)
#pragma unroll
            for (int v = 0; v < 4; v++) acc[ma][na][v] = 0.f;

    const __nv_bfloat16* Ah = g_atth + (size_t)b * PIX * CCH;
    const __nv_bfloat16* Al = g_attl + (size_t)b * PIX * CCH;

    auto issue = [&](int c, int s) {
        const int c0 = c * KC;
        const u32 ub = sb0 + s * STG4;
#pragma unroll
        for (int t = 0; t < 2; t++) {
            int idx = tid + t * 256;
            int row = idx >> 2, seg = idx & 3;
            size_t srcA = ((size_t)(p0 + row)) * CCH + c0 + seg * 8;
            size_t srcB = ((size_t)(n0 + row)) * CCH + c0 + seg * 8;
            u32 doff = (u32)(row * (KCPAD * 2) + seg * 16);
            cp16(ub + doff, Ah + srcA);
            cp16(ub + STAGE_B + doff, Al + srcA);
            cp16(ub + 2 * STAGE_B + doff, g_w2h + srcB);
            cp16(ub + 3 * STAGE_B + doff, g_w2l + srcB);
        }
        CP_COMMIT();
    };

    issue(0, 0);
#pragma unroll 1
    for (int c = 0; c < NCHUNK; c++) {
        const int s = c & 1;
        if (c + 1 < NCHUNK) { issue(c + 1, s ^ 1); CP_WAIT1(); }
        else                { CP_WAIT0(); }
        __syncthreads();

        const u32 uAh = sb0 + s * STG4;
        const u32 uAl = uAh + STAGE_B;
        const u32 uBh = uAh + 2 * STAGE_B;
        const u32 uBl = uAh + 3 * STAGE_B;
#pragma unroll
        for (int ks = 0; ks < 2; ks++) {
            const u32 ko = ks * 32;
            u32 ah[2][4], al[2][4];
            ldsm4(ah[0], uAh + offA + ko);
            ldsm4(ah[1], uAh + offA + ko + 16 * KCPAD * 2);
            ldsm4(al[0], uAl + offA + ko);
            ldsm4(al[1], uAl + offA + ko + 16 * KCPAD * 2);
#pragma unroll
            for (int ng = 0; ng < 4; ng++) {
                u32 bh[4], bl[4];
                ldsm4(bh, uBh + offB + ko + ng * (16 * KCPAD * 2));
                ldsm4(bl, uBl + offB + ko + ng * (16 * KCPAD * 2));
#pragma unroll
                for (int h = 0; h < 2; h++) {
                    const u32* bhf = bh + 2 * h;
                    const u32* blf = bl + 2 * h;
                    int na = ng * 2 + h;
#pragma unroll
                    for (int ma = 0; ma < 2; ma++) {
                        mma_bf16(acc[ma][na], ah[ma], bhf);
                        mma_bf16(acc[ma][na], ah[ma], blf);
                        mma_bf16(acc[ma][na], al[ma], bhf);
                    }
                }
            }
        }
        __syncthreads();
    }

    // Epilogue: y[b][n][p]
    const int r = lane >> 2;
    const int cp = (lane & 3) * 2;
#pragma unroll
    for (int ma = 0; ma < 2; ma++) {
#pragma unroll
        for (int na = 0; na < 8; na++) {
#pragma unroll
            for (int v = 0; v < 4; v++) {
                int m = p0 + warp_m * 32 + ma * 16 + r + (v >> 1) * 8;
                int n = n0 + warp_n * 64 + na * 8 + cp + (v & 1);
                y[((size_t)(b * CCH + n)) * PIX + m] = acc[ma][na][v] + b2[n];
            }
        }
    }
}

// ---------------------------------------------------------------------------
extern "C" void kernel_launch(void* const* d_in, const int* in_sizes, int n_in,
                              void* d_out, int out_size) {
    const float* x  = (const float*)d_in[0];
    const float* W1 = (const float*)d_in[1];
    const float* b1 = (const float*)d_in[2];
    const float* W2 = (const float*)d_in[3];
    const float* b2 = (const float*)d_in[4];
    float* y = (float*)d_out;

    cudaFuncSetAttribute(attn_mma,
                         cudaFuncAttributeMaxDynamicSharedMemorySize, ATTN_SMEM);
    cudaFuncSetAttribute(qkv_mma,
                         cudaFuncAttributeMaxDynamicSharedMemorySize, GEMM_SMEM);
    cudaFuncSetAttribute(proj_mma,
                         cudaFuncAttributeMaxDynamicSharedMemorySize, GEMM_SMEM);

    __nv_bfloat16 *w1h, *w1l, *w2h, *w2l;
    cudaGetSymbolAddress((void**)&w1h, g_w1h);
    cudaGetSymbolAddress((void**)&w1l, g_w1l);
    cudaGetSymbolAddress((void**)&w2h, g_w2h);
    cudaGetSymbolAddress((void**)&w2l, g_w2l);

    // 0) fp32 -> bf16 hi/lo splits
    conv_x<<<dim3(PIX / 32, CCH / 32, BATCH), dim3(32, 8)>>>(x);
    conv_w<<<(768 * CCH + 255) / 256, 256>>>(W1, w1h, w1l, 768 * CCH);
    conv_w<<<(CCH * CCH + 255) / 256, 256>>>(W2, w2h, w2l, CCH * CCH);

    // 1) QKV: M=4096 (x128), N=768 (x128), per batch
    qkv_mma<<<dim3(PIX / 128, 768 / 128, BATCH), 256, GEMM_SMEM>>>(b1);

    // 2) Attention: (64 windows, 8 heads, 16 batches)
    attn_mma<<<dim3(NWIN * NWIN, NH, BATCH), 128, ATTN_SMEM>>>();

    // 3) Output projection: N=256 (x128)
    proj_mma<<<dim3(PIX / 128, CCH / 128, BATCH), 256, GEMM_SMEM>>>(b2, y);
}

// round 14
// speedup vs baseline: 1.5001x; 1.5001x over previous
#include <cuda_runtime.h>
#include <cuda_bf16.h>
#include <math.h>

#define NH    8
#define EDIM  32
#define WS    8
#define MO    12
#define NKEY  (MO*MO)      // 144
#define BATCH 16
#define CCH   256
#define HH    64
#define WW    64
#define PIX   (HH*WW)      // 4096
#define NWIN  8

typedef unsigned long long u64;
typedef unsigned int u32;

// Scratch buffers
__device__ float g_Q[BATCH * NH * PIX * EDIM];    // (b, head, pixel, e)
__device__ float g_K[BATCH * NH * PIX * EDIM];
__device__ float g_V[BATCH * NH * PIX * EDIM];

// bf16 hi/lo split scratch
__device__ __nv_bfloat16 g_xh[BATCH * PIX * CCH];   // x transposed: (b, p, c)
__device__ __nv_bfloat16 g_xl[BATCH * PIX * CCH];
__device__ __nv_bfloat16 g_w1h[768 * CCH];          // (n, k)
__device__ __nv_bfloat16 g_w1l[768 * CCH];
__device__ __nv_bfloat16 g_w2h[CCH * CCH];
__device__ __nv_bfloat16 g_w2l[CCH * CCH];
__device__ __nv_bfloat16 g_atth[BATCH * PIX * CCH]; // attn out hi (b, p, c)
__device__ __nv_bfloat16 g_attl[BATCH * PIX * CCH]; // attn out lo

// ---- fast exp on FMA pipe ----
__device__ __forceinline__ float fast_exp(float x) {
    float y = fmaxf(x * 1.4426950408889634f, -125.0f);
    float z = y + 12582912.0f;
    int   n = __float_as_int(z) - 0x4B400000;
    float f = y - (z - 12582912.0f);
    float p = 1.540353039338161e-4f;
    p = fmaf(p, f, 0.0013333558146428443f);
    p = fmaf(p, f, 0.009618129107628477f);
    p = fmaf(p, f, 0.05550410866482158f);
    p = fmaf(p, f, 0.2402265069591007f);
    p = fmaf(p, f, 0.6931471805599453f);
    p = fmaf(p, f, 1.0f);
    return p * __int_as_float((n + 127) << 23);
}

// ---- mma.sync helpers ----
__device__ __forceinline__ u32 smem_u32(const void* p) {
    u32 a; asm("{ .reg .u64 t; cvta.to.shared.u64 t, %1; cvt.u32.u64 %0, t; }"
               : "=r"(a) : "l"(p));
    return a;
}
__device__ __forceinline__ void ldsm4(u32* r, u32 addr) {
    asm volatile("ldmatrix.sync.aligned.m8n8.x4.shared.b16 {%0,%1,%2,%3}, [%4];"
                 : "=r"(r[0]), "=r"(r[1]), "=r"(r[2]), "=r"(r[3]) : "r"(addr));
}
__device__ __forceinline__ void ldsm4t(u32* r, u32 addr) {
    asm volatile("ldmatrix.sync.aligned.m8n8.x4.trans.shared.b16 {%0,%1,%2,%3}, [%4];"
                 : "=r"(r[0]), "=r"(r[1]), "=r"(r[2]), "=r"(r[3]) : "r"(addr));
}
__device__ __forceinline__ void mma_bf16(float* d, const u32* a, const u32* b) {
    asm volatile(
        "mma.sync.aligned.m16n8k16.row.col.f32.bf16.bf16.f32 "
        "{%0,%1,%2,%3}, {%4,%5,%6,%7}, {%8,%9}, {%0,%1,%2,%3};"
        : "+f"(d[0]), "+f"(d[1]), "+f"(d[2]), "+f"(d[3])
        : "r"(a[0]), "r"(a[1]), "r"(a[2]), "r"(a[3]), "r"(b[0]), "r"(b[1]));
}
__device__ __forceinline__ void cp16(u32 dst, const void* src) {
    asm volatile("cp.async.cg.shared.global [%0], [%1], 16;"
                 :: "r"(dst), "l"(src));
}
#define CP_COMMIT() asm volatile("cp.async.commit_group;" ::: "memory")
#define CP_WAIT0()  asm volatile("cp.async.wait_group 0;" ::: "memory")

__device__ __forceinline__ void split_bf16(float v, __nv_bfloat16& hi, __nv_bfloat16& lo) {
    hi = __float2bfloat16(v);
    lo = __float2bfloat16(v - __bfloat162float(hi));
}
// pack two fp32 -> bf16x2 register
__device__ __forceinline__ u32 pkbf2(float lo, float hi) {
    u32 d; asm("cvt.rn.bf16x2.f32 %0, %1, %2;" : "=r"(d) : "f"(hi), "f"(lo));
    return d;
}
__device__ __forceinline__ void split4(float4 v, uint2& hi, uint2& lo) {
    hi.x = pkbf2(v.x, v.y);
    hi.y = pkbf2(v.z, v.w);
    __nv_bfloat162 h0 = *(__nv_bfloat162*)&hi.x;
    __nv_bfloat162 h1 = *(__nv_bfloat162*)&hi.y;
    lo.x = pkbf2(v.x - __bfloat162float(h0.x), v.y - __bfloat162float(h0.y));
    lo.y = pkbf2(v.z - __bfloat162float(h1.x), v.w - __bfloat162float(h1.y));
}

// GEMM smem (serial KC=64, 2 CTAs/SM — R8/R11 proven config)
#define KPAD 72
#define TILE_B (128 * KPAD * 2)       // 18432 bytes
#define GEMM_SMEM (4 * TILE_B)        // 73728 bytes

// ---------------------------------------------------------------------------
// Conversion kernels
// ---------------------------------------------------------------------------
__global__ void conv_x(const float* __restrict__ x) {
    __shared__ float tile[32][33];
    const int b  = blockIdx.z;
    const int p0 = blockIdx.x * 32;
    const int c0 = blockIdx.y * 32;
    const int tx = threadIdx.x, ty = threadIdx.y;   // 32 x 8
    const float* xb = x + ((size_t)b * CCH + c0) * PIX + p0;
#pragma unroll
    for (int i = 0; i < 32; i += 8)
        tile[ty + i][tx] = xb[(size_t)(ty + i) * PIX + tx];
    __syncthreads();
#pragma unroll
    for (int i = 0; i < 32; i += 8) {
        int p = p0 + ty + i;
        float v = tile[tx][ty + i];
        __nv_bfloat16 hi, lo; split_bf16(v, hi, lo);
        size_t o = ((size_t)b * PIX + p) * CCH + c0 + tx;
        g_xh[o] = hi;
        g_xl[o] = lo;
    }
}

__global__ void conv_w(const float* __restrict__ w, __nv_bfloat16* __restrict__ wh,
                       __nv_bfloat16* __restrict__ wl, int n) {
    int i = blockIdx.x * 256 + threadIdx.x;
    if (i < n) {
        __nv_bfloat16 hi, lo; split_bf16(w[i], hi, lo);
        wh[i] = hi;
        wl[i] = lo;
    }
}

// ---------------------------------------------------------------------------
// Kernel 1: QKV projection (mma.sync bf16x3 + cp.async, 2 CTAs/SM). R8-exact.
// ---------------------------------------------------------------------------
__global__ __launch_bounds__(256, 2) void qkv_mma(const float* __restrict__ b1) {
    extern __shared__ char smem[];
    char* sAh = smem;
    char* sAl = smem + TILE_B;
    char* sBh = smem + 2 * TILE_B;
    char* sBl = smem + 3 * TILE_B;
    const u32 uAh = smem_u32(sAh), uAl = smem_u32(sAl);
    const u32 uBh = smem_u32(sBh), uBl = smem_u32(sBl);

    const int tid = threadIdx.x;
    const int lane = tid & 31, wid = tid >> 5;
    const int warp_m = wid >> 1, warp_n = wid & 1;
    const int b  = blockIdx.z;
    const int p0 = blockIdx.x * 128;
    const int n0 = blockIdx.y * 128;

    const int g = lane >> 3, rr = lane & 7;
    const u32 offA = (u32)(((warp_m * 32 + rr + (g & 1) * 8) * KPAD + (g >> 1) * 8) * 2);
    const u32 offB = (u32)(((warp_n * 64 + (g >> 1) * 8 + rr) * KPAD + (g & 1) * 8) * 2);

    float acc[2][8][4];
#pragma unroll
    for (int ma = 0; ma < 2; ma++)
#pragma unroll
        for (int na = 0; na < 8; na++)
#pragma unroll
            for (int v = 0; v < 4; v++) acc[ma][na][v] = 0.f;

    const __nv_bfloat16* Ah = g_xh + (size_t)b * PIX * CCH;
    const __nv_bfloat16* Al = g_xl + (size_t)b * PIX * CCH;

    for (int c0 = 0; c0 < CCH; c0 += 64) {
#pragma unroll
        for (int t = 0; t < 4; t++) {
            int idx = tid + t * 256;
            int row = idx >> 3, seg = idx & 7;
            size_t srcA = ((size_t)(p0 + row)) * CCH + c0 + seg * 8;
            size_t srcB = ((size_t)(n0 + row)) * CCH + c0 + seg * 8;
            u32 doff = (u32)(row * (KPAD * 2) + seg * 16);
            cp16(uAh + doff, Ah + srcA);
            cp16(uAl + doff, Al + srcA);
            cp16(uBh + doff, g_w1h + srcB);
            cp16(uBl + doff, g_w1l + srcB);
        }
        CP_COMMIT();
        CP_WAIT0();
        __syncthreads();

#pragma unroll
        for (int ks = 0; ks < 4; ks++) {
            const u32 ko = ks * 32;
            u32 ah[2][4], al[2][4];
            ldsm4(ah[0], uAh + offA + ko);
            ldsm4(ah[1], uAh + offA + ko + 16 * KPAD * 2);
            ldsm4(al[0], uAl + offA + ko);
            ldsm4(al[1], uAl + offA + ko + 16 * KPAD * 2);
#pragma unroll
            for (int ng = 0; ng < 4; ng++) {
                u32 bh[4], bl[4];
                ldsm4(bh, uBh + offB + ko + ng * (16 * KPAD * 2));
                ldsm4(bl, uBl + offB + ko + ng * (16 * KPAD * 2));
#pragma unroll
                for (int h = 0; h < 2; h++) {
                    const u32* bhf = bh + 2 * h;
                    const u32* blf = bl + 2 * h;
                    int na = ng * 2 + h;
#pragma unroll
                    for (int ma = 0; ma < 2; ma++) {
                        mma_bf16(acc[ma][na], ah[ma], bhf);
                        mma_bf16(acc[ma][na], ah[ma], blf);
                        mma_bf16(acc[ma][na], al[ma], bhf);
                    }
                }
            }
        }
        __syncthreads();
    }

    // Epilogue: scatter fp32 into Q/K/V
    const int r = lane >> 2;
    const int cp = (lane & 3) * 2;
#pragma unroll
    for (int ma = 0; ma < 2; ma++) {
#pragma unroll
        for (int na = 0; na < 8; na++) {
#pragma unroll
            for (int v = 0; v < 4; v++) {
                int m  = p0 + warp_m * 32 + ma * 16 + r + (v >> 1) * 8;
                int oc = n0 + warp_n * 64 + na * 8 + cp + (v & 1);
                float val = acc[ma][na][v] + b1[oc];
                int type = oc % 3;
                int ch   = oc / 3;
                int head = ch >> 5;
                int e    = ch & 31;
                float* dst = (type == 0) ? g_Q : (type == 1) ? g_K : g_V;
                dst[((size_t)(b * NH + head) * PIX + m) * EDIM + e] = val;
            }
        }
    }
}

// ---------------------------------------------------------------------------
// Kernel 2: windowed attention, mma.sync bf16x3, register-resident P.
// R11-exact (passing, ~150us).
// ---------------------------------------------------------------------------
#define EPAD 40              // e-stride (elements); row = 80 B
#define A_QH  0
#define A_QL  5120
#define A_KH  10240
#define A_KL  21760
#define A_VH  33280
#define A_VL  44800
#define ATTN_SMEM 56320

__global__ __launch_bounds__(128) void attn_mma() {
    extern __shared__ char sm[];
    const u32 sb = smem_u32(sm);

    const int b    = blockIdx.z;
    const int head = blockIdx.y;
    const int wi   = blockIdx.x >> 3;
    const int wj   = blockIdx.x & 7;
    const int tid  = threadIdx.x;
    const int lane = tid & 31;
    const int warp = tid >> 5;

    const size_t hb = (size_t)(b * NH + head) * PIX * EDIM;
    const float* Qg = g_Q + hb;
    const float* Kg = g_K + hb;
    const float* Vg = g_V + hb;
    const float scale = 0.17677669529663687f;   // 1/sqrt(32), folded into Q

    for (int idx = tid; idx < 64 * 8; idx += 128) {
        int q = idx >> 3, e4 = (idx & 7) * 4;
        int r = wi * 8 + (q >> 3);
        int c = wj * 8 + (q & 7);
        float4 v = *(const float4*)(Qg + (size_t)(r * WW + c) * EDIM + e4);
        v.x *= scale; v.y *= scale; v.z *= scale; v.w *= scale;
        uint2 hi, lo; split4(v, hi, lo);
        u32 doff = (u32)((q * EPAD + e4) * 2);
        *(uint2*)(sm + A_QH + doff) = hi;
        *(uint2*)(sm + A_QL + doff) = lo;
    }
    for (int idx = tid; idx < NKEY * 8; idx += 128) {
        int k = idx >> 3, e4 = (idx & 7) * 4;
        int kr = k / MO, kc = k % MO;
        int r = wi * 8 - 2 + kr;
        int c = wj * 8 - 2 + kc;
        float4 kv = make_float4(0.f, 0.f, 0.f, 0.f);
        float4 vv = kv;
        if (r >= 0 && r < HH && c >= 0 && c < WW) {
            size_t off = (size_t)(r * WW + c) * EDIM + e4;
            kv = *(const float4*)(Kg + off);
            vv = *(const float4*)(Vg + off);
        }
        uint2 khi, klo, vhi, vlo;
        split4(kv, khi, klo);
        split4(vv, vhi, vlo);
        u32 doff = (u32)((k * EPAD + e4) * 2);
        *(uint2*)(sm + A_KH + doff) = khi;
        *(uint2*)(sm + A_KL + doff) = klo;
        *(uint2*)(sm + A_VH + doff) = vhi;
        *(uint2*)(sm + A_VL + doff) = vlo;
    }
    __syncthreads();

    const int g = lane >> 3, rr = lane & 7;

    float acc[18][4];
#pragma unroll
    for (int na = 0; na < 18; na++)
#pragma unroll
        for (int v = 0; v < 4; v++) acc[na][v] = 0.f;
    {
        const u32 aoff = (u32)(((warp * 16 + rr + (g & 1) * 8) * EPAD + (g >> 1) * 8) * 2);
        const u32 boff = (u32)((((g >> 1) * 8 + rr) * EPAD + (g & 1) * 8) * 2);
#pragma unroll
        for (int ks = 0; ks < 2; ks++) {
            const u32 ko = ks * 32;
            u32 ah[4], al[4];
            ldsm4(ah, sb + A_QH + aoff + ko);
            ldsm4(al, sb + A_QL + aoff + ko);
#pragma unroll
            for (int ng = 0; ng < 9; ng++) {
                u32 bh[4], bl[4];
                const u32 nb = ng * (16 * EPAD * 2);
                ldsm4(bh, sb + A_KH + boff + nb + ko);
                ldsm4(bl, sb + A_KL + boff + nb + ko);
#pragma unroll
                for (int h = 0; h < 2; h++) {
                    int na = ng * 2 + h;
                    mma_bf16(acc[na], ah, bh + 2 * h);
                    mma_bf16(acc[na], ah, bl + 2 * h);
                    mma_bf16(acc[na], al, bh + 2 * h);
                }
            }
        }
    }

    {
        float m0 = -1e30f, m1 = -1e30f;
#pragma unroll
        for (int na = 0; na < 18; na++) {
            m0 = fmaxf(m0, fmaxf(acc[na][0], acc[na][1]));
            m1 = fmaxf(m1, fmaxf(acc[na][2], acc[na][3]));
        }
        m0 = fmaxf(m0, __shfl_xor_sync(0xFFFFFFFFu, m0, 1));
        m0 = fmaxf(m0, __shfl_xor_sync(0xFFFFFFFFu, m0, 2));
        m1 = fmaxf(m1, __shfl_xor_sync(0xFFFFFFFFu, m1, 1));
        m1 = fmaxf(m1, __shfl_xor_sync(0xFFFFFFFFu, m1, 2));
        float s0 = 0.f, s1 = 0.f;
#pragma unroll
        for (int na = 0; na < 18; na++) {
            acc[na][0] = fast_exp(acc[na][0] - m0);
            acc[na][1] = fast_exp(acc[na][1] - m0);
            acc[na][2] = fast_exp(acc[na][2] - m1);
            acc[na][3] = fast_exp(acc[na][3] - m1);
            s0 += acc[na][0] + acc[na][1];
            s1 += acc[na][2] + acc[na][3];
        }
        s0 += __shfl_xor_sync(0xFFFFFFFFu, s0, 1);
        s0 += __shfl_xor_sync(0xFFFFFFFFu, s0, 2);
        s1 += __shfl_xor_sync(0xFFFFFFFFu, s1, 1);
        s1 += __shfl_xor_sync(0xFFFFFFFFu, s1, 2);
        float i0 = 1.f / s0, i1 = 1.f / s1;
#pragma unroll
        for (int na = 0; na < 18; na++) {
            acc[na][0] *= i0;
            acc[na][1] *= i0;
            acc[na][2] *= i1;
            acc[na][3] *= i1;
        }
    }

    {
        float av[4][4];
#pragma unroll
        for (int na = 0; na < 4; na++)
#pragma unroll
            for (int v = 0; v < 4; v++) av[na][v] = 0.f;

        const u32 vrow = (u32)(((g & 1) * 8 + rr) * EPAD + (g >> 1) * 8);
#pragma unroll
        for (int ks = 0; ks < 9; ks++) {
            u32 ph[4], pl[4];
            {
                float c00 = acc[2 * ks][0],     c01 = acc[2 * ks][1];
                float c02 = acc[2 * ks][2],     c03 = acc[2 * ks][3];
                float c10 = acc[2 * ks + 1][0], c11 = acc[2 * ks + 1][1];
                float c12 = acc[2 * ks + 1][2], c13 = acc[2 * ks + 1][3];
                ph[0] = pkbf2(c00, c01);
                ph[1] = pkbf2(c02, c03);
                ph[2] = pkbf2(c10, c11);
                ph[3] = pkbf2(c12, c13);
                __nv_bfloat162 h0 = *(__nv_bfloat162*)&ph[0];
                __nv_bfloat162 h1 = *(__nv_bfloat162*)&ph[1];
                __nv_bfloat162 h2 = *(__nv_bfloat162*)&ph[2];
                __nv_bfloat162 h3 = *(__nv_bfloat162*)&ph[3];
                pl[0] = pkbf2(c00 - __bfloat162float(h0.x), c01 - __bfloat162float(h0.y));
                pl[1] = pkbf2(c02 - __bfloat162float(h1.x), c03 - __bfloat162float(h1.y));
                pl[2] = pkbf2(c10 - __bfloat162float(h2.x), c11 - __bfloat162float(h2.y));
                pl[3] = pkbf2(c12 - __bfloat162float(h3.x), c13 - __bfloat162float(h3.y));
            }
            const u32 kb = (u32)(ks * 16 * EPAD * 2);
#pragma unroll
            for (int half = 0; half < 2; half++) {
                u32 vh[4], vl[4];
                const u32 addr = kb + (vrow + half * 16) * 2;
                ldsm4t(vh, sb + A_VH + addr);
                ldsm4t(vl, sb + A_VL + addr);
#pragma unroll
                for (int h = 0; h < 2; h++) {
                    int na = half * 2 + h;
                    mma_bf16(av[na], ph, vh + 2 * h);
                    mma_bf16(av[na], ph, vl + 2 * h);
                    mma_bf16(av[na], pl, vh + 2 * h);
                }
            }
        }

        const int r0 = lane >> 2;
        const int e0 = (lane & 3) * 2;
#pragma unroll
        for (int half = 0; half < 2; half++) {
            int q = warp * 16 + r0 + half * 8;
            int r = wi * 8 + (q >> 3);
            int c = wj * 8 + (q & 7);
            size_t base = ((size_t)b * PIX + r * WW + c) * CCH + head * EDIM;
#pragma unroll
            for (int na = 0; na < 4; na++) {
                int e = na * 8 + e0;
                float o0 = av[na][half * 2 + 0];
                float o1 = av[na][half * 2 + 1];
                u32 hh = pkbf2(o0, o1);
                __nv_bfloat162 hv = *(__nv_bfloat162*)&hh;
                u32 ll = pkbf2(o0 - __bfloat162float(hv.x),
                               o1 - __bfloat162float(hv.y));
                *(u32*)((char*)(g_atth + base + e)) = hh;
                *(u32*)((char*)(g_attl + base + e)) = ll;
            }
        }
    }
}

// ---------------------------------------------------------------------------
// Kernel 3: output projection (mma.sync bf16x3 + cp.async, 2 CTAs/SM). R8-exact.
// ---------------------------------------------------------------------------
__global__ __launch_bounds__(256, 2) void proj_mma(const float* __restrict__ b2,
                                                   float* __restrict__ y) {
    extern __shared__ char smem[];
    char* sAh = smem;
    char* sAl = smem + TILE_B;
    char* sBh = smem + 2 * TILE_B;
    char* sBl = smem + 3 * TILE_B;
    const u32 uAh = smem_u32(sAh), uAl = smem_u32(sAl);
    const u32 uBh = smem_u32(sBh), uBl = smem_u32(sBl);

    const int tid = threadIdx.x;
    const int lane = tid & 31, wid = tid >> 5;
    const int warp_m = wid >> 1, warp_n = wid & 1;
    const int b  = blockIdx.z;
    const int p0 = blockIdx.x * 128;
    const int n0 = blockIdx.y * 128;

    const int g = lane >> 3, rr = lane & 7;
    const u32 offA = (u32)(((warp_m * 32 + rr + (g & 1) * 8) * KPAD + (g >> 1) * 8) * 2);
    const u32 offB = (u32)(((warp_n * 64 + (g >> 1) * 8 + rr) * KPAD + (g & 1) * 8) * 2);

    float acc[2][8][4];
#pragma unroll
    for (int ma = 0; ma < 2; ma++)
#pragma unroll
        for (int na = 0; na < 8; na++)
#pragma unroll
            for (int v = 0; v < 4; v++) acc[ma][na][v] = 0.f;

    const __nv_bfloat16* Ah = g_atth + (size_t)b * PIX * CCH;
    const __nv_bfloat16* Al = g_attl + (size_t)b * PIX * CCH;

    for (int c0 = 0; c0 < CCH; c0 += 64) {
#pragma unroll
        for (int t = 0; t < 4; t++) {
            int idx = tid + t * 256;
            int row = idx >> 3, seg = idx & 7;
            size_t srcA = ((size_t)(p0 + row)) * CCH + c0 + seg * 8;
            size_t srcB = ((size_t)(n0 + row)) * CCH + c0 + seg * 8;
            u32 doff = (u32)(row * (KPAD * 2) + seg * 16);
            cp16(uAh + doff, Ah + srcA);
            cp16(uAl + doff, Al + srcA);
            cp16(uBh + doff, g_w2h + srcB);
            cp16(uBl + doff, g_w2l + srcB);
        }
        CP_COMMIT();
        CP_WAIT0();
        __syncthreads();

#pragma unroll
        for (int ks = 0; ks < 4; ks++) {
            const u32 ko = ks * 32;
            u32 ah[2][4], al[2][4];
            ldsm4(ah[0], uAh + offA + ko);
            ldsm4(ah[1], uAh + offA + ko + 16 * KPAD * 2);
            ldsm4(al[0], uAl + offA + ko);
            ldsm4(al[1], uAl + offA + ko + 16 * KPAD * 2);
#pragma unroll
            for (int ng = 0; ng < 4; ng++) {
                u32 bh[4], bl[4];
                ldsm4(bh, uBh + offB + ko + ng * (16 * KPAD * 2));
                ldsm4(bl, uBl + offB + ko + ng * (16 * KPAD * 2));
#pragma unroll
                for (int h = 0; h < 2; h++) {
                    const u32* bhf = bh + 2 * h;
                    const u32* blf = bl + 2 * h;
                    int na = ng * 2 + h;
#pragma unroll
                    for (int ma = 0; ma < 2; ma++) {
                        mma_bf16(acc[ma][na], ah[ma], bhf);
                        mma_bf16(acc[ma][na], ah[ma], blf);
                        mma_bf16(acc[ma][na], al[ma], bhf);
                    }
                }
            }
        }
        __syncthreads();
    }

    // Epilogue: y[b][n][p]
    const int r = lane >> 2;
    const int cp = (lane & 3) * 2;
#pragma unroll
    for (int ma = 0; ma < 2; ma++) {
#pragma unroll
        for (int na = 0; na < 8; na++) {
#pragma unroll
            for (int v = 0; v < 4; v++) {
                int m = p0 + warp_m * 32 + ma * 16 + r + (v >> 1) * 8;
                int n = n0 + warp_n * 64 + na * 8 + cp + (v & 1);
                y[((size_t)(b * CCH + n)) * PIX + m] = acc[ma][na][v] + b2[n];
            }
        }
    }
}

// ---------------------------------------------------------------------------
extern "C" void kernel_launch(void* const* d_in, const int* in_sizes, int n_in,
                              void* d_out, int out_size) {
    const float* x  = (const float*)d_in[0];
    const float* W1 = (const float*)d_in[1];
    const float* b1 = (const float*)d_in[2];
    const float* W2 = (const float*)d_in[3];
    const float* b2 = (const float*)d_in[4];
    float* y = (float*)d_out;

    cudaFuncSetAttribute(attn_mma,
                         cudaFuncAttributeMaxDynamicSharedMemorySize, ATTN_SMEM);
    cudaFuncSetAttribute(qkv_mma,
                         cudaFuncAttributeMaxDynamicSharedMemorySize, GEMM_SMEM);
    cudaFuncSetAttribute(proj_mma,
                         cudaFuncAttributeMaxDynamicSharedMemorySize, GEMM_SMEM);

    __nv_bfloat16 *w1h, *w1l, *w2h, *w2l;
    cudaGetSymbolAddress((void**)&w1h, g_w1h);
    cudaGetSymbolAddress((void**)&w1l, g_w1l);
    cudaGetSymbolAddress((void**)&w2h, g_w2h);
    cudaGetSymbolAddress((void**)&w2l, g_w2l);

    // 0) fp32 -> bf16 hi/lo splits
    conv_x<<<dim3(PIX / 32, CCH / 32, BATCH), dim3(32, 8)>>>(x);
    conv_w<<<(768 * CCH + 255) / 256, 256>>>(W1, w1h, w1l, 768 * CCH);
    conv_w<<<(CCH * CCH + 255) / 256, 256>>>(W2, w2h, w2l, CCH * CCH);

    // 1) QKV: M=4096 (x128), N=768 (x128), per batch
    qkv_mma<<<dim3(PIX / 128, 768 / 128, BATCH), 256, GEMM_SMEM>>>(b1);

    // 2) Attention: (64 windows, 8 heads, 16 batches)
    attn_mma<<<dim3(NWIN * NWIN, NH, BATCH), 128, ATTN_SMEM>>>();

    // 3) Output projection: N=256 (x128)
    proj_mma<<<dim3(PIX / 128, CCH / 128, BATCH), 256, GEMM_SMEM>>>(b2, y);
}

// round 16
// speedup vs baseline: 1.8700x; 1.2466x over previous
#include <cuda_runtime.h>
#include <cuda_fp16.h>
#include <math.h>

#define NH    8
#define EDIM  32
#define WS    8
#define MO    12
#define NKEY  (MO*MO)      // 144
#define BATCH 16
#define CCH   256
#define HH    64
#define WW    64
#define PIX   (HH*WW)      // 4096
#define NWIN  8

typedef unsigned long long u64;
typedef unsigned int u32;

// Scratch buffers
__device__ float g_Q[BATCH * NH * PIX * EDIM];    // (b, head, pixel, e)
__device__ float g_K[BATCH * NH * PIX * EDIM];
__device__ float g_V[BATCH * NH * PIX * EDIM];

// fp16 split scratch: activations hi/lo, weights hi only
__device__ __half g_xh[BATCH * PIX * CCH];   // x transposed: (b, p, c)
__device__ __half g_xl[BATCH * PIX * CCH];
__device__ __half g_w1h[768 * CCH];          // (n, k)
__device__ __half g_w2h[CCH * CCH];
__device__ __half g_atth[BATCH * PIX * CCH]; // attn out hi (b, p, c)
__device__ __half g_attl[BATCH * PIX * CCH]; // attn out lo

// ---- fast exp on FMA pipe ----
__device__ __forceinline__ float fast_exp(float x) {
    float y = fmaxf(x * 1.4426950408889634f, -125.0f);
    float z = y + 12582912.0f;
    int   n = __float_as_int(z) - 0x4B400000;
    float f = y - (z - 12582912.0f);
    float p = 1.540353039338161e-4f;
    p = fmaf(p, f, 0.0013333558146428443f);
    p = fmaf(p, f, 0.009618129107628477f);
    p = fmaf(p, f, 0.05550410866482158f);
    p = fmaf(p, f, 0.2402265069591007f);
    p = fmaf(p, f, 0.6931471805599453f);
    p = fmaf(p, f, 1.0f);
    return p * __int_as_float((n + 127) << 23);
}

// ---- mma.sync helpers (fp16 path) ----
__device__ __forceinline__ u32 smem_u32(const void* p) {
    u32 a; asm("{ .reg .u64 t; cvta.to.shared.u64 t, %1; cvt.u32.u64 %0, t; }"
               : "=r"(a) : "l"(p));
    return a;
}
__device__ __forceinline__ void ldsm4(u32* r, u32 addr) {
    asm volatile("ldmatrix.sync.aligned.m8n8.x4.shared.b16 {%0,%1,%2,%3}, [%4];"
                 : "=r"(r[0]), "=r"(r[1]), "=r"(r[2]), "=r"(r[3]) : "r"(addr));
}
__device__ __forceinline__ void ldsm4t(u32* r, u32 addr) {
    asm volatile("ldmatrix.sync.aligned.m8n8.x4.trans.shared.b16 {%0,%1,%2,%3}, [%4];"
                 : "=r"(r[0]), "=r"(r[1]), "=r"(r[2]), "=r"(r[3]) : "r"(addr));
}
__device__ __forceinline__ void mma_f16(float* d, const u32* a, const u32* b) {
    asm volatile(
        "mma.sync.aligned.m16n8k16.row.col.f32.f16.f16.f32 "
        "{%0,%1,%2,%3}, {%4,%5,%6,%7}, {%8,%9}, {%0,%1,%2,%3};"
        : "+f"(d[0]), "+f"(d[1]), "+f"(d[2]), "+f"(d[3])
        : "r"(a[0]), "r"(a[1]), "r"(a[2]), "r"(a[3]), "r"(b[0]), "r"(b[1]));
}
__device__ __forceinline__ void cp16(u32 dst, const void* src) {
    asm volatile("cp.async.cg.shared.global [%0], [%1], 16;"
                 :: "r"(dst), "l"(src));
}
#define CP_COMMIT() asm volatile("cp.async.commit_group;" ::: "memory")
#define CP_WAIT0()  asm volatile("cp.async.wait_group 0;" ::: "memory")

__device__ __forceinline__ void split_f16(float v, __half& hi, __half& lo) {
    hi = __float2half_rn(v);
    lo = __float2half_rn(v - __half2float(hi));
}
// pack two fp32 -> f16x2 register (lo arg in low half, hi arg in high half)
__device__ __forceinline__ u32 pkf16(float lo, float hi) {
    u32 d; asm("cvt.rn.f16x2.f32 %0, %1, %2;" : "=r"(d) : "f"(hi), "f"(lo));
    return d;
}
// split float4 into packed hi (2x u32) and lo (2x u32) f16x2 words
__device__ __forceinline__ void split4(float4 v, uint2& hi, uint2& lo) {
    hi.x = pkf16(v.x, v.y);
    hi.y = pkf16(v.z, v.w);
    __half2 h0 = *(__half2*)&hi.x;
    __half2 h1 = *(__half2*)&hi.y;
    lo.x = pkf16(v.x - __half2float(h0.x), v.y - __half2float(h0.y));
    lo.y = pkf16(v.z - __half2float(h1.x), v.w - __half2float(h1.y));
}

// GEMM smem: 3 arrays (Ahi, Alo, Bhi), serial KC=64, 2 CTAs/SM
#define KPAD 72
#define TILE_B (128 * KPAD * 2)       // 18432 bytes
#define GEMM_SMEM (3 * TILE_B)        // 55296 bytes

// ---------------------------------------------------------------------------
// Conversion kernels
// ---------------------------------------------------------------------------
__global__ void conv_x(const float* __restrict__ x) {
    __shared__ float tile[32][33];
    const int b  = blockIdx.z;
    const int p0 = blockIdx.x * 32;
    const int c0 = blockIdx.y * 32;
    const int tx = threadIdx.x, ty = threadIdx.y;   // 32 x 8
    const float* xb = x + ((size_t)b * CCH + c0) * PIX + p0;
#pragma unroll
    for (int i = 0; i < 32; i += 8)
        tile[ty + i][tx] = xb[(size_t)(ty + i) * PIX + tx];
    __syncthreads();
#pragma unroll
    for (int i = 0; i < 32; i += 8) {
        int p = p0 + ty + i;
        float v = tile[tx][ty + i];
        __half hi, lo; split_f16(v, hi, lo);
        size_t o = ((size_t)b * PIX + p) * CCH + c0 + tx;
        g_xh[o] = hi;
        g_xl[o] = lo;
    }
}

__global__ void conv_w(const float* __restrict__ w, __half* __restrict__ wh, int n) {
    int i = blockIdx.x * 256 + threadIdx.x;
    if (i < n) wh[i] = __float2half_rn(w[i]);
}

// ---------------------------------------------------------------------------
// Kernel 1: QKV projection. fp16x2: D = (Ahi + Alo) * Bhi. cp.async, 2 CTAs/SM.
// ---------------------------------------------------------------------------
__global__ __launch_bounds__(256, 2) void qkv_mma(const float* __restrict__ b1) {
    extern __shared__ char smem[];
    char* sAh = smem;
    char* sAl = smem + TILE_B;
    char* sBh = smem + 2 * TILE_B;
    const u32 uAh = smem_u32(sAh), uAl = smem_u32(sAl), uBh = smem_u32(sBh);

    const int tid = threadIdx.x;
    const int lane = tid & 31, wid = tid >> 5;
    const int warp_m = wid >> 1, warp_n = wid & 1;
    const int b  = blockIdx.z;
    const int p0 = blockIdx.x * 128;
    const int n0 = blockIdx.y * 128;

    const int g = lane >> 3, rr = lane & 7;
    const u32 offA = (u32)(((warp_m * 32 + rr + (g & 1) * 8) * KPAD + (g >> 1) * 8) * 2);
    const u32 offB = (u32)(((warp_n * 64 + (g >> 1) * 8 + rr) * KPAD + (g & 1) * 8) * 2);

    float acc[2][8][4];
#pragma unroll
    for (int ma = 0; ma < 2; ma++)
#pragma unroll
        for (int na = 0; na < 8; na++)
#pragma unroll
            for (int v = 0; v < 4; v++) acc[ma][na][v] = 0.f;

    const __half* Ah = g_xh + (size_t)b * PIX * CCH;
    const __half* Al = g_xl + (size_t)b * PIX * CCH;

    for (int c0 = 0; c0 < CCH; c0 += 64) {
#pragma unroll
        for (int t = 0; t < 4; t++) {
            int idx = tid + t * 256;
            int row = idx >> 3, seg = idx & 7;
            size_t srcA = ((size_t)(p0 + row)) * CCH + c0 + seg * 8;
            size_t srcB = ((size_t)(n0 + row)) * CCH + c0 + seg * 8;
            u32 doff = (u32)(row * (KPAD * 2) + seg * 16);
            cp16(uAh + doff, Ah + srcA);
            cp16(uAl + doff, Al + srcA);
            cp16(uBh + doff, g_w1h + srcB);
        }
        CP_COMMIT();
        CP_WAIT0();
        __syncthreads();

#pragma unroll
        for (int ks = 0; ks < 4; ks++) {
            const u32 ko = ks * 32;
            u32 ah[2][4], al[2][4];
            ldsm4(ah[0], uAh + offA + ko);
            ldsm4(ah[1], uAh + offA + ko + 16 * KPAD * 2);
            ldsm4(al[0], uAl + offA + ko);
            ldsm4(al[1], uAl + offA + ko + 16 * KPAD * 2);
#pragma unroll
            for (int ng = 0; ng < 4; ng++) {
                u32 bh[4];
                ldsm4(bh, uBh + offB + ko + ng * (16 * KPAD * 2));
#pragma unroll
                for (int h = 0; h < 2; h++) {
                    const u32* bhf = bh + 2 * h;
                    int na = ng * 2 + h;
#pragma unroll
                    for (int ma = 0; ma < 2; ma++) {
                        mma_f16(acc[ma][na], ah[ma], bhf);
                        mma_f16(acc[ma][na], al[ma], bhf);
                    }
                }
            }
        }
        __syncthreads();
    }

    // Epilogue: scatter fp32 into Q/K/V
    const int r = lane >> 2;
    const int cp = (lane & 3) * 2;
#pragma unroll
    for (int ma = 0; ma < 2; ma++) {
#pragma unroll
        for (int na = 0; na < 8; na++) {
#pragma unroll
            for (int v = 0; v < 4; v++) {
                int m  = p0 + warp_m * 32 + ma * 16 + r + (v >> 1) * 8;
                int oc = n0 + warp_n * 64 + na * 8 + cp + (v & 1);
                float val = acc[ma][na][v] + b1[oc];
                int type = oc % 3;
                int ch   = oc / 3;
                int head = ch >> 5;
                int e    = ch & 31;
                float* dst = (type == 0) ? g_Q : (type == 1) ? g_K : g_V;
                dst[((size_t)(b * NH + head) * PIX + m) * EDIM + e] = val;
            }
        }
    }
}

// ---------------------------------------------------------------------------
// Kernel 2: windowed attention, fp16 mma, register-resident P.
// Q hi/lo (exact), K single, V single. QK = 2 mma/step, AV = 1 mma/step.
// ---------------------------------------------------------------------------
#define EPAD 40              // e-stride (elements); row = 80 B
#define A_QH  0              // 64*80  = 5120
#define A_QL  5120
#define A_KH  10240          // 144*80 = 11520
#define A_VH  21760
#define ATTN_SMEM 33280

__global__ __launch_bounds__(128) void attn_mma() {
    extern __shared__ char sm[];
    const u32 sb = smem_u32(sm);

    const int b    = blockIdx.z;
    const int head = blockIdx.y;
    const int wi   = blockIdx.x >> 3;
    const int wj   = blockIdx.x & 7;
    const int tid  = threadIdx.x;
    const int lane = tid & 31;
    const int warp = tid >> 5;

    const size_t hb = (size_t)(b * NH + head) * PIX * EDIM;
    const float* Qg = g_Q + hb;
    const float* Kg = g_K + hb;
    const float* Vg = g_V + hb;
    const float scale = 0.17677669529663687f;   // 1/sqrt(32), folded into Q

    // ---- Load Q (64x32, scaled, hi/lo), K/V (144x32, single fp16)
    for (int idx = tid; idx < 64 * 8; idx += 128) {
        int q = idx >> 3, e4 = (idx & 7) * 4;
        int r = wi * 8 + (q >> 3);
        int c = wj * 8 + (q & 7);
        float4 v = *(const float4*)(Qg + (size_t)(r * WW + c) * EDIM + e4);
        v.x *= scale; v.y *= scale; v.z *= scale; v.w *= scale;
        uint2 hi, lo; split4(v, hi, lo);
        u32 doff = (u32)((q * EPAD + e4) * 2);
        *(uint2*)(sm + A_QH + doff) = hi;
        *(uint2*)(sm + A_QL + doff) = lo;
    }
    for (int idx = tid; idx < NKEY * 8; idx += 128) {
        int k = idx >> 3, e4 = (idx & 7) * 4;
        int kr = k / MO, kc = k % MO;
        int r = wi * 8 - 2 + kr;
        int c = wj * 8 - 2 + kc;
        float4 kv = make_float4(0.f, 0.f, 0.f, 0.f);
        float4 vv = kv;
        if (r >= 0 && r < HH && c >= 0 && c < WW) {
            size_t off = (size_t)(r * WW + c) * EDIM + e4;
            kv = *(const float4*)(Kg + off);
            vv = *(const float4*)(Vg + off);
        }
        uint2 kh, vh;
        kh.x = pkf16(kv.x, kv.y); kh.y = pkf16(kv.z, kv.w);
        vh.x = pkf16(vv.x, vv.y); vh.y = pkf16(vv.z, vv.w);
        u32 doff = (u32)((k * EPAD + e4) * 2);
        *(uint2*)(sm + A_KH + doff) = kh;
        *(uint2*)(sm + A_VH + doff) = vh;
    }
    __syncthreads();

    const int g = lane >> 3, rr = lane & 7;

    // ---- QK^T: warp m-atom (16 q) x 18 n-atoms (144 keys) x 2 ksteps, 2-term
    float acc[18][4];
#pragma unroll
    for (int na = 0; na < 18; na++)
#pragma unroll
        for (int v = 0; v < 4; v++) acc[na][v] = 0.f;
    {
        const u32 aoff = (u32)(((warp * 16 + rr + (g & 1) * 8) * EPAD + (g >> 1) * 8) * 2);
        const u32 boff = (u32)((((g >> 1) * 8 + rr) * EPAD + (g & 1) * 8) * 2);
#pragma unroll
        for (int ks = 0; ks < 2; ks++) {
            const u32 ko = ks * 32;
            u32 ah[4], al[4];
            ldsm4(ah, sb + A_QH + aoff + ko);
            ldsm4(al, sb + A_QL + aoff + ko);
#pragma unroll
            for (int ng = 0; ng < 9; ng++) {
                u32 bh[4];
                const u32 nb = ng * (16 * EPAD * 2);
                ldsm4(bh, sb + A_KH + boff + nb + ko);
#pragma unroll
                for (int h = 0; h < 2; h++) {
                    int na = ng * 2 + h;
                    mma_f16(acc[na], ah, bh + 2 * h);
                    mma_f16(acc[na], al, bh + 2 * h);
                }
            }
        }
    }

    // ---- fragment softmax
    {
        float m0 = -1e30f, m1 = -1e30f;
#pragma unroll
        for (int na = 0; na < 18; na++) {
            m0 = fmaxf(m0, fmaxf(acc[na][0], acc[na][1]));
            m1 = fmaxf(m1, fmaxf(acc[na][2], acc[na][3]));
        }
        m0 = fmaxf(m0, __shfl_xor_sync(0xFFFFFFFFu, m0, 1));
        m0 = fmaxf(m0, __shfl_xor_sync(0xFFFFFFFFu, m0, 2));
        m1 = fmaxf(m1, __shfl_xor_sync(0xFFFFFFFFu, m1, 1));
        m1 = fmaxf(m1, __shfl_xor_sync(0xFFFFFFFFu, m1, 2));
        float s0 = 0.f, s1 = 0.f;
#pragma unroll
        for (int na = 0; na < 18; na++) {
            acc[na][0] = fast_exp(acc[na][0] - m0);
            acc[na][1] = fast_exp(acc[na][1] - m0);
            acc[na][2] = fast_exp(acc[na][2] - m1);
            acc[na][3] = fast_exp(acc[na][3] - m1);
            s0 += acc[na][0] + acc[na][1];
            s1 += acc[na][2] + acc[na][3];
        }
        s0 += __shfl_xor_sync(0xFFFFFFFFu, s0, 1);
        s0 += __shfl_xor_sync(0xFFFFFFFFu, s0, 2);
        s1 += __shfl_xor_sync(0xFFFFFFFFu, s1, 1);
        s1 += __shfl_xor_sync(0xFFFFFFFFu, s1, 2);
        float i0 = 1.f / s0, i1 = 1.f / s1;
#pragma unroll
        for (int na = 0; na < 18; na++) {
            acc[na][0] *= i0;
            acc[na][1] *= i0;
            acc[na][2] *= i1;
            acc[na][3] *= i1;
        }
    }

    // ---- A@V: P single fp16 packed from registers; V via ldmatrix.trans
    {
        float av[4][4];
#pragma unroll
        for (int na = 0; na < 4; na++)
#pragma unroll
            for (int v = 0; v < 4; v++) av[na][v] = 0.f;

        const u32 vrow = (u32)(((g & 1) * 8 + rr) * EPAD + (g >> 1) * 8);
#pragma unroll
        for (int ks = 0; ks < 9; ks++) {
            u32 ph[4];
            ph[0] = pkf16(acc[2 * ks][0],     acc[2 * ks][1]);
            ph[1] = pkf16(acc[2 * ks][2],     acc[2 * ks][3]);
            ph[2] = pkf16(acc[2 * ks + 1][0], acc[2 * ks + 1][1]);
            ph[3] = pkf16(acc[2 * ks + 1][2], acc[2 * ks + 1][3]);
            const u32 kb = (u32)(ks * 16 * EPAD * 2);
#pragma unroll
            for (int half = 0; half < 2; half++) {
                u32 vh[4];
                const u32 addr = kb + (vrow + half * 16) * 2;
                ldsm4t(vh, sb + A_VH + addr);
#pragma unroll
                for (int h = 0; h < 2; h++) {
                    int na = half * 2 + h;
                    mma_f16(av[na], ph, vh + 2 * h);
                }
            }
        }

        // epilogue: write fp16 hi/lo att (A side of proj stays exact)
        const int r0 = lane >> 2;
        const int e0 = (lane & 3) * 2;
#pragma unroll
        for (int half = 0; half < 2; half++) {
            int q = warp * 16 + r0 + half * 8;
            int r = wi * 8 + (q >> 3);
            int c = wj * 8 + (q & 7);
            size_t base = ((size_t)b * PIX + r * WW + c) * CCH + head * EDIM;
#pragma unroll
            for (int na = 0; na < 4; na++) {
                int e = na * 8 + e0;
                float o0 = av[na][half * 2 + 0];
                float o1 = av[na][half * 2 + 1];
                u32 hh = pkf16(o0, o1);
                __half2 hv = *(__half2*)&hh;
                u32 ll = pkf16(o0 - __half2float(hv.x),
                               o1 - __half2float(hv.y));
                *(u32*)((char*)(g_atth + base + e)) = hh;
                *(u32*)((char*)(g_attl + base + e)) = ll;
            }
        }
    }
}

// ---------------------------------------------------------------------------
// Kernel 3: output projection. fp16x2: D = (atth + attl) * W2h.
// ---------------------------------------------------------------------------
__global__ __launch_bounds__(256, 2) void proj_mma(const float* __restrict__ b2,
                                                   float* __restrict__ y) {
    extern __shared__ char smem[];
    char* sAh = smem;
    char* sAl = smem + TILE_B;
    char* sBh = smem + 2 * TILE_B;
    const u32 uAh = smem_u32(sAh), uAl = smem_u32(sAl), uBh = smem_u32(sBh);

    const int tid = threadIdx.x;
    const int lane = tid & 31, wid = tid >> 5;
    const int warp_m = wid >> 1, warp_n = wid & 1;
    const int b  = blockIdx.z;
    const int p0 = blockIdx.x * 128;
    const int n0 = blockIdx.y * 128;

    const int g = lane >> 3, rr = lane & 7;
    const u32 offA = (u32)(((warp_m * 32 + rr + (g & 1) * 8) * KPAD + (g >> 1) * 8) * 2);
    const u32 offB = (u32)(((warp_n * 64 + (g >> 1) * 8 + rr) * KPAD + (g & 1) * 8) * 2);

    float acc[2][8][4];
#pragma unroll
    for (int ma = 0; ma < 2; ma++)
#pragma unroll
        for (int na = 0; na < 8; na++)
#pragma unroll
            for (int v = 0; v < 4; v++) acc[ma][na][v] = 0.f;

    const __half* Ah = g_atth + (size_t)b * PIX * CCH;
    const __half* Al = g_attl + (size_t)b * PIX * CCH;

    for (int c0 = 0; c0 < CCH; c0 += 64) {
#pragma unroll
        for (int t = 0; t < 4; t++) {
            int idx = tid + t * 256;
            int row = idx >> 3, seg = idx & 7;
            size_t srcA = ((size_t)(p0 + row)) * CCH + c0 + seg * 8;
            size_t srcB = ((size_t)(n0 + row)) * CCH + c0 + seg * 8;
            u32 doff = (u32)(row * (KPAD * 2) + seg * 16);
            cp16(uAh + doff, Ah + srcA);
            cp16(uAl + doff, Al + srcA);
            cp16(uBh + doff, g_w2h + srcB);
        }
        CP_COMMIT();
        CP_WAIT0();
        __syncthreads();

#pragma unroll
        for (int ks = 0; ks < 4; ks++) {
            const u32 ko = ks * 32;
            u32 ah[2][4], al[2][4];
            ldsm4(ah[0], uAh + offA + ko);
            ldsm4(ah[1], uAh + offA + ko + 16 * KPAD * 2);
            ldsm4(al[0], uAl + offA + ko);
            ldsm4(al[1], uAl + offA + ko + 16 * KPAD * 2);
#pragma unroll
            for (int ng = 0; ng < 4; ng++) {
                u32 bh[4];
                ldsm4(bh, uBh + offB + ko + ng * (16 * KPAD * 2));
#pragma unroll
                for (int h = 0; h < 2; h++) {
                    const u32* bhf = bh + 2 * h;
                    int na = ng * 2 + h;
#pragma unroll
                    for (int ma = 0; ma < 2; ma++) {
                        mma_f16(acc[ma][na], ah[ma], bhf);
                        mma_f16(acc[ma][na], al[ma], bhf);
                    }
                }
            }
        }
        __syncthreads();
    }

    // Epilogue: y[b][n][p]
    const int r = lane >> 2;
    const int cp = (lane & 3) * 2;
#pragma unroll
    for (int ma = 0; ma < 2; ma++) {
#pragma unroll
        for (int na = 0; na < 8; na++) {
#pragma unroll
            for (int v = 0; v < 4; v++) {
                int m = p0 + warp_m * 32 + ma * 16 + r + (v >> 1) * 8;
                int n = n0 + warp_n * 64 + na * 8 + cp + (v & 1);
                y[((size_t)(b * CCH + n)) * PIX + m] = acc[ma][na][v] + b2[n];
            }
        }
    }
}

// ---------------------------------------------------------------------------
extern "C" void kernel_launch(void* const* d_in, const int* in_sizes, int n_in,
                              void* d_out, int out_size) {
    const float* x  = (const float*)d_in[0];
    const float* W1 = (const float*)d_in[1];
    const float* b1 = (const float*)d_in[2];
    const float* W2 = (const float*)d_in[3];
    const float* b2 = (const float*)d_in[4];
    float* y = (float*)d_out;

    cudaFuncSetAttribute(attn_mma,
                         cudaFuncAttributeMaxDynamicSharedMemorySize, ATTN_SMEM);
    cudaFuncSetAttribute(qkv_mma,
                         cudaFuncAttributeMaxDynamicSharedMemorySize, GEMM_SMEM);
    cudaFuncSetAttribute(proj_mma,
                         cudaFuncAttributeMaxDynamicSharedMemorySize, GEMM_SMEM);

    __half *w1h, *w2h;
    cudaGetSymbolAddress((void**)&w1h, g_w1h);
    cudaGetSymbolAddress((void**)&w2h, g_w2h);

    // 0) fp32 -> fp16 splits (activations hi/lo, weights hi only)
    conv_x<<<dim3(PIX / 32, CCH / 32, BATCH), dim3(32, 8)>>>(x);
    conv_w<<<(768 * CCH + 255) / 256, 256>>>(W1, w1h, 768 * CCH);
    conv_w<<<(CCH * CCH + 255) / 256, 256>>>(W2, w2h, CCH * CCH);

    // 1) QKV: M=4096 (x128), N=768 (x128), per batch
    qkv_mma<<<dim3(PIX / 128, 768 / 128, BATCH), 256, GEMM_SMEM>>>(b1);

    // 2) Attention: (64 windows, 8 heads, 16 batches)
    attn_mma<<<dim3(NWIN * NWIN, NH, BATCH), 128, ATTN_SMEM>>>();

    // 3) Output projection: N=256 (x128)
    proj_mma<<<dim3(PIX / 128, CCH / 128, BATCH), 256, GEMM_SMEM>>>(b2, y);
}

// round 17
// speedup vs baseline: 2.1668x; 1.1587x over previous
#include <cuda_runtime.h>
#include <cuda_fp16.h>
#include <math.h>

#define NH    8
#define EDIM  32
#define WS    8
#define MO    12
#define NKEY  (MO*MO)      // 144
#define BATCH 16
#define CCH   256
#define HH    64
#define WW    64
#define PIX   (HH*WW)      // 4096
#define NWIN  8

typedef unsigned long long u64;
typedef unsigned int u32;

// Scratch buffers
__device__ float g_Q[BATCH * NH * PIX * EDIM];    // (b, head, pixel, e)
__device__ float g_K[BATCH * NH * PIX * EDIM];
__device__ float g_V[BATCH * NH * PIX * EDIM];

// fp16 scratch (single precision stream everywhere; Q hi/lo only in-kernel)
__device__ __half g_xh[BATCH * PIX * CCH];   // x transposed: (b, p, c)
__device__ __half g_w1h[768 * CCH];          // (n, k)
__device__ __half g_w2h[CCH * CCH];
__device__ __half g_atth[BATCH * PIX * CCH]; // attn out (b, p, c)

// ---- fast exp on FMA pipe ----
__device__ __forceinline__ float fast_exp(float x) {
    float y = fmaxf(x * 1.4426950408889634f, -125.0f);
    float z = y + 12582912.0f;
    int   n = __float_as_int(z) - 0x4B400000;
    float f = y - (z - 12582912.0f);
    float p = 1.540353039338161e-4f;
    p = fmaf(p, f, 0.0013333558146428443f);
    p = fmaf(p, f, 0.009618129107628477f);
    p = fmaf(p, f, 0.05550410866482158f);
    p = fmaf(p, f, 0.2402265069591007f);
    p = fmaf(p, f, 0.6931471805599453f);
    p = fmaf(p, f, 1.0f);
    return p * __int_as_float((n + 127) << 23);
}

// ---- mma.sync helpers (fp16 path) ----
__device__ __forceinline__ u32 smem_u32(const void* p) {
    u32 a; asm("{ .reg .u64 t; cvta.to.shared.u64 t, %1; cvt.u32.u64 %0, t; }"
               : "=r"(a) : "l"(p));
    return a;
}
__device__ __forceinline__ void ldsm4(u32* r, u32 addr) {
    asm volatile("ldmatrix.sync.aligned.m8n8.x4.shared.b16 {%0,%1,%2,%3}, [%4];"
                 : "=r"(r[0]), "=r"(r[1]), "=r"(r[2]), "=r"(r[3]) : "r"(addr));
}
__device__ __forceinline__ void ldsm4t(u32* r, u32 addr) {
    asm volatile("ldmatrix.sync.aligned.m8n8.x4.trans.shared.b16 {%0,%1,%2,%3}, [%4];"
                 : "=r"(r[0]), "=r"(r[1]), "=r"(r[2]), "=r"(r[3]) : "r"(addr));
}
__device__ __forceinline__ void mma_f16(float* d, const u32* a, const u32* b) {
    asm volatile(
        "mma.sync.aligned.m16n8k16.row.col.f32.f16.f16.f32 "
        "{%0,%1,%2,%3}, {%4,%5,%6,%7}, {%8,%9}, {%0,%1,%2,%3};"
        : "+f"(d[0]), "+f"(d[1]), "+f"(d[2]), "+f"(d[3])
        : "r"(a[0]), "r"(a[1]), "r"(a[2]), "r"(a[3]), "r"(b[0]), "r"(b[1]));
}
__device__ __forceinline__ void cp16(u32 dst, const void* src) {
    asm volatile("cp.async.cg.shared.global [%0], [%1], 16;"
                 :: "r"(dst), "l"(src));
}
#define CP_COMMIT() asm volatile("cp.async.commit_group;" ::: "memory")
#define CP_WAIT0()  asm volatile("cp.async.wait_group 0;" ::: "memory")

// pack two fp32 -> f16x2 register (lo arg in low half, hi arg in high half)
__device__ __forceinline__ u32 pkf16(float lo, float hi) {
    u32 d; asm("cvt.rn.f16x2.f32 %0, %1, %2;" : "=r"(d) : "f"(hi), "f"(lo));
    return d;
}
// split float4 into packed hi (2x u32) and lo (2x u32) f16x2 words
__device__ __forceinline__ void split4(float4 v, uint2& hi, uint2& lo) {
    hi.x = pkf16(v.x, v.y);
    hi.y = pkf16(v.z, v.w);
    __half2 h0 = *(__half2*)&hi.x;
    __half2 h1 = *(__half2*)&hi.y;
    lo.x = pkf16(v.x - __half2float(h0.x), v.y - __half2float(h0.y));
    lo.y = pkf16(v.z - __half2float(h1.x), v.w - __half2float(h1.y));
}

// GEMM smem: 2 arrays (A, B), serial KC=64, 2 CTAs/SM
#define KPAD 72
#define TILE_B (128 * KPAD * 2)       // 18432 bytes
#define GEMM_SMEM (2 * TILE_B)        // 36864 bytes

// ---------------------------------------------------------------------------
// Conversion kernels
// ---------------------------------------------------------------------------
__global__ void conv_x(const float* __restrict__ x) {
    __shared__ float tile[32][33];
    const int b  = blockIdx.z;
    const int p0 = blockIdx.x * 32;
    const int c0 = blockIdx.y * 32;
    const int tx = threadIdx.x, ty = threadIdx.y;   // 32 x 8
    const float* xb = x + ((size_t)b * CCH + c0) * PIX + p0;
#pragma unroll
    for (int i = 0; i < 32; i += 8)
        tile[ty + i][tx] = xb[(size_t)(ty + i) * PIX + tx];
    __syncthreads();
#pragma unroll
    for (int i = 0; i < 32; i += 8) {
        int p = p0 + ty + i;
        g_xh[((size_t)b * PIX + p) * CCH + c0 + tx] =
            __float2half_rn(tile[tx][ty + i]);
    }
}

__global__ void conv_w(const float* __restrict__ w, __half* __restrict__ wh, int n) {
    int i = blockIdx.x * 256 + threadIdx.x;
    if (i < n) wh[i] = __float2half_rn(w[i]);
}

// ---------------------------------------------------------------------------
// Kernel 1: QKV projection. Pure fp16 A*B, cp.async, 2 CTAs/SM.
// ---------------------------------------------------------------------------
__global__ __launch_bounds__(256, 2) void qkv_mma(const float* __restrict__ b1) {
    extern __shared__ char smem[];
    char* sA = smem;
    char* sB = smem + TILE_B;
    const u32 uA = smem_u32(sA), uB = smem_u32(sB);

    const int tid = threadIdx.x;
    const int lane = tid & 31, wid = tid >> 5;
    const int warp_m = wid >> 1, warp_n = wid & 1;
    const int b  = blockIdx.z;
    const int p0 = blockIdx.x * 128;
    const int n0 = blockIdx.y * 128;

    const int g = lane >> 3, rr = lane & 7;
    const u32 offA = (u32)(((warp_m * 32 + rr + (g & 1) * 8) * KPAD + (g >> 1) * 8) * 2);
    const u32 offB = (u32)(((warp_n * 64 + (g >> 1) * 8 + rr) * KPAD + (g & 1) * 8) * 2);

    float acc[2][8][4];
#pragma unroll
    for (int ma = 0; ma < 2; ma++)
#pragma unroll
        for (int na = 0; na < 8; na++)
#pragma unroll
            for (int v = 0; v < 4; v++) acc[ma][na][v] = 0.f;

    const __half* Ag = g_xh + (size_t)b * PIX * CCH;

    for (int c0 = 0; c0 < CCH; c0 += 64) {
        // A: 128 rows x 64 k + B: 128 rows x 64 k; 8 cp16 per row-pair group
#pragma unroll
        for (int t = 0; t < 4; t++) {
            int idx = tid + t * 256;          // 0..1023
            int row = idx >> 3, seg = idx & 7;
            u32 doff = (u32)(row * (KPAD * 2) + seg * 16);
            cp16(uA + doff, Ag + ((size_t)(p0 + row)) * CCH + c0 + seg * 8);
            cp16(uB + doff, g_w1h + ((size_t)(n0 + row)) * CCH + c0 + seg * 8);
        }
        CP_COMMIT();
        CP_WAIT0();
        __syncthreads();

#pragma unroll
        for (int ks = 0; ks < 4; ks++) {
            const u32 ko = ks * 32;
            u32 ah[2][4];
            ldsm4(ah[0], uA + offA + ko);
            ldsm4(ah[1], uA + offA + ko + 16 * KPAD * 2);
#pragma unroll
            for (int ng = 0; ng < 4; ng++) {
                u32 bh[4];
                ldsm4(bh, uB + offB + ko + ng * (16 * KPAD * 2));
#pragma unroll
                for (int h = 0; h < 2; h++) {
                    const u32* bhf = bh + 2 * h;
                    int na = ng * 2 + h;
#pragma unroll
                    for (int ma = 0; ma < 2; ma++)
                        mma_f16(acc[ma][na], ah[ma], bhf);
                }
            }
        }
        __syncthreads();
    }

    // Epilogue: scatter fp32 into Q/K/V
    const int r = lane >> 2;
    const int cp = (lane & 3) * 2;
#pragma unroll
    for (int ma = 0; ma < 2; ma++) {
#pragma unroll
        for (int na = 0; na < 8; na++) {
#pragma unroll
            for (int v = 0; v < 4; v++) {
                int m  = p0 + warp_m * 32 + ma * 16 + r + (v >> 1) * 8;
                int oc = n0 + warp_n * 64 + na * 8 + cp + (v & 1);
                float val = acc[ma][na][v] + b1[oc];
                int type = oc % 3;
                int ch   = oc / 3;
                int head = ch >> 5;
                int e    = ch & 31;
                float* dst = (type == 0) ? g_Q : (type == 1) ? g_K : g_V;
                dst[((size_t)(b * NH + head) * PIX + m) * EDIM + e] = val;
            }
        }
    }
}

// ---------------------------------------------------------------------------
// Kernel 2: windowed attention, fp16 mma, register-resident P.
// Q hi/lo (exact vs g_Q), K single, V single. QK = 2 mma/step, AV = 1.
// Epilogue writes single fp16 att.
// ---------------------------------------------------------------------------
#define EPAD 40              // e-stride (elements); row = 80 B
#define A_QH  0              // 64*80  = 5120
#define A_QL  5120
#define A_KH  10240          // 144*80 = 11520
#define A_VH  21760
#define ATTN_SMEM 33280

__global__ __launch_bounds__(128) void attn_mma() {
    extern __shared__ char sm[];
    const u32 sb = smem_u32(sm);

    const int b    = blockIdx.z;
    const int head = blockIdx.y;
    const int wi   = blockIdx.x >> 3;
    const int wj   = blockIdx.x & 7;
    const int tid  = threadIdx.x;
    const int lane = tid & 31;
    const int warp = tid >> 5;

    const size_t hb = (size_t)(b * NH + head) * PIX * EDIM;
    const float* Qg = g_Q + hb;
    const float* Kg = g_K + hb;
    const float* Vg = g_V + hb;
    const float scale = 0.17677669529663687f;   // 1/sqrt(32), folded into Q

    // ---- Load Q (64x32, scaled, hi/lo), K/V (144x32, single fp16)
    for (int idx = tid; idx < 64 * 8; idx += 128) {
        int q = idx >> 3, e4 = (idx & 7) * 4;
        int r = wi * 8 + (q >> 3);
        int c = wj * 8 + (q & 7);
        float4 v = *(const float4*)(Qg + (size_t)(r * WW + c) * EDIM + e4);
        v.x *= scale; v.y *= scale; v.z *= scale; v.w *= scale;
        uint2 hi, lo; split4(v, hi, lo);
        u32 doff = (u32)((q * EPAD + e4) * 2);
        *(uint2*)(sm + A_QH + doff) = hi;
        *(uint2*)(sm + A_QL + doff) = lo;
    }
    for (int idx = tid; idx < NKEY * 8; idx += 128) {
        int k = idx >> 3, e4 = (idx & 7) * 4;
        int kr = k / MO, kc = k % MO;
        int r = wi * 8 - 2 + kr;
        int c = wj * 8 - 2 + kc;
        float4 kv = make_float4(0.f, 0.f, 0.f, 0.f);
        float4 vv = kv;
        if (r >= 0 && r < HH && c >= 0 && c < WW) {
            size_t off = (size_t)(r * WW + c) * EDIM + e4;
            kv = *(const float4*)(Kg + off);
            vv = *(const float4*)(Vg + off);
        }
        uint2 kh, vh;
        kh.x = pkf16(kv.x, kv.y); kh.y = pkf16(kv.z, kv.w);
        vh.x = pkf16(vv.x, vv.y); vh.y = pkf16(vv.z, vv.w);
        u32 doff = (u32)((k * EPAD + e4) * 2);
        *(uint2*)(sm + A_KH + doff) = kh;
        *(uint2*)(sm + A_VH + doff) = vh;
    }
    __syncthreads();

    const int g = lane >> 3, rr = lane & 7;

    // ---- QK^T: warp m-atom (16 q) x 18 n-atoms (144 keys) x 2 ksteps, 2-term
    float acc[18][4];
#pragma unroll
    for (int na = 0; na < 18; na++)
#pragma unroll
        for (int v = 0; v < 4; v++) acc[na][v] = 0.f;
    {
        const u32 aoff = (u32)(((warp * 16 + rr + (g & 1) * 8) * EPAD + (g >> 1) * 8) * 2);
        const u32 boff = (u32)((((g >> 1) * 8 + rr) * EPAD + (g & 1) * 8) * 2);
#pragma unroll
        for (int ks = 0; ks < 2; ks++) {
            const u32 ko = ks * 32;
            u32 ah[4], al[4];
            ldsm4(ah, sb + A_QH + aoff + ko);
            ldsm4(al, sb + A_QL + aoff + ko);
#pragma unroll
            for (int ng = 0; ng < 9; ng++) {
                u32 bh[4];
                const u32 nb = ng * (16 * EPAD * 2);
                ldsm4(bh, sb + A_KH + boff + nb + ko);
#pragma unroll
                for (int h = 0; h < 2; h++) {
                    int na = ng * 2 + h;
                    mma_f16(acc[na], ah, bh + 2 * h);
                    mma_f16(acc[na], al, bh + 2 * h);
                }
            }
        }
    }

    // ---- fragment softmax
    {
        float m0 = -1e30f, m1 = -1e30f;
#pragma unroll
        for (int na = 0; na < 18; na++) {
            m0 = fmaxf(m0, fmaxf(acc[na][0], acc[na][1]));
            m1 = fmaxf(m1, fmaxf(acc[na][2], acc[na][3]));
        }
        m0 = fmaxf(m0, __shfl_xor_sync(0xFFFFFFFFu, m0, 1));
        m0 = fmaxf(m0, __shfl_xor_sync(0xFFFFFFFFu, m0, 2));
        m1 = fmaxf(m1, __shfl_xor_sync(0xFFFFFFFFu, m1, 1));
        m1 = fmaxf(m1, __shfl_xor_sync(0xFFFFFFFFu, m1, 2));
        float s0 = 0.f, s1 = 0.f;
#pragma unroll
        for (int na = 0; na < 18; na++) {
            acc[na][0] = fast_exp(acc[na][0] - m0);
            acc[na][1] = fast_exp(acc[na][1] - m0);
            acc[na][2] = fast_exp(acc[na][2] - m1);
            acc[na][3] = fast_exp(acc[na][3] - m1);
            s0 += acc[na][0] + acc[na][1];
            s1 += acc[na][2] + acc[na][3];
        }
        s0 += __shfl_xor_sync(0xFFFFFFFFu, s0, 1);
        s0 += __shfl_xor_sync(0xFFFFFFFFu, s0, 2);
        s1 += __shfl_xor_sync(0xFFFFFFFFu, s1, 1);
        s1 += __shfl_xor_sync(0xFFFFFFFFu, s1, 2);
        float i0 = 1.f / s0, i1 = 1.f / s1;
#pragma unroll
        for (int na = 0; na < 18; na++) {
            acc[na][0] *= i0;
            acc[na][1] *= i0;
            acc[na][2] *= i1;
            acc[na][3] *= i1;
        }
    }

    // ---- A@V: P single fp16 packed from registers; V via ldmatrix.trans
    {
        float av[4][4];
#pragma unroll
        for (int na = 0; na < 4; na++)
#pragma unroll
            for (int v = 0; v < 4; v++) av[na][v] = 0.f;

        const u32 vrow = (u32)(((g & 1) * 8 + rr) * EPAD + (g >> 1) * 8);
#pragma unroll
        for (int ks = 0; ks < 9; ks++) {
            u32 ph[4];
            ph[0] = pkf16(acc[2 * ks][0],     acc[2 * ks][1]);
            ph[1] = pkf16(acc[2 * ks][2],     acc[2 * ks][3]);
            ph[2] = pkf16(acc[2 * ks + 1][0], acc[2 * ks + 1][1]);
            ph[3] = pkf16(acc[2 * ks + 1][2], acc[2 * ks + 1][3]);
            const u32 kb = (u32)(ks * 16 * EPAD * 2);
#pragma unroll
            for (int half = 0; half < 2; half++) {
                u32 vh[4];
                const u32 addr = kb + (vrow + half * 16) * 2;
                ldsm4t(vh, sb + A_VH + addr);
#pragma unroll
                for (int h = 0; h < 2; h++) {
                    int na = half * 2 + h;
                    mma_f16(av[na], ph, vh + 2 * h);
                }
            }
        }

        // epilogue: write single fp16 att
        const int r0 = lane >> 2;
        const int e0 = (lane & 3) * 2;
#pragma unroll
        for (int half = 0; half < 2; half++) {
            int q = warp * 16 + r0 + half * 8;
            int r = wi * 8 + (q >> 3);
            int c = wj * 8 + (q & 7);
            size_t base = ((size_t)b * PIX + r * WW + c) * CCH + head * EDIM;
#pragma unroll
            for (int na = 0; na < 4; na++) {
                int e = na * 8 + e0;
                u32 hh = pkf16(av[na][half * 2 + 0], av[na][half * 2 + 1]);
                *(u32*)((char*)(g_atth + base + e)) = hh;
            }
        }
    }
}

// ---------------------------------------------------------------------------
// Kernel 3: output projection. Pure fp16 A*B.
// ---------------------------------------------------------------------------
__global__ __launch_bounds__(256, 2) void proj_mma(const float* __restrict__ b2,
                                                   float* __restrict__ y) {
    extern __shared__ char smem[];
    char* sA = smem;
    char* sB = smem + TILE_B;
    const u32 uA = smem_u32(sA), uB = smem_u32(sB);

    const int tid = threadIdx.x;
    const int lane = tid & 31, wid = tid >> 5;
    const int warp_m = wid >> 1, warp_n = wid & 1;
    const int b  = blockIdx.z;
    const int p0 = blockIdx.x * 128;
    const int n0 = blockIdx.y * 128;

    const int g = lane >> 3, rr = lane & 7;
    const u32 offA = (u32)(((warp_m * 32 + rr + (g & 1) * 8) * KPAD + (g >> 1) * 8) * 2);
    const u32 offB = (u32)(((warp_n * 64 + (g >> 1) * 8 + rr) * KPAD + (g & 1) * 8) * 2);

    float acc[2][8][4];
#pragma unroll
    for (int ma = 0; ma < 2; ma++)
#pragma unroll
        for (int na = 0; na < 8; na++)
#pragma unroll
            for (int v = 0; v < 4; v++) acc[ma][na][v] = 0.f;

    const __half* Ag = g_atth + (size_t)b * PIX * CCH;

    for (int c0 = 0; c0 < CCH; c0 += 64) {
#pragma unroll
        for (int t = 0; t < 4; t++) {
            int idx = tid + t * 256;
            int row = idx >> 3, seg = idx & 7;
            u32 doff = (u32)(row * (KPAD * 2) + seg * 16);
            cp16(uA + doff, Ag + ((size_t)(p0 + row)) * CCH + c0 + seg * 8);
            cp16(uB + doff, g_w2h + ((size_t)(n0 + row)) * CCH + c0 + seg * 8);
        }
        CP_COMMIT();
        CP_WAIT0();
        __syncthreads();

#pragma unroll
        for (int ks = 0; ks < 4; ks++) {
            const u32 ko = ks * 32;
            u32 ah[2][4];
            ldsm4(ah[0], uA + offA + ko);
            ldsm4(ah[1], uA + offA + ko + 16 * KPAD * 2);
#pragma unroll
            for (int ng = 0; ng < 4; ng++) {
                u32 bh[4];
                ldsm4(bh, uB + offB + ko + ng * (16 * KPAD * 2));
#pragma unroll
                for (int h = 0; h < 2; h++) {
                    const u32* bhf = bh + 2 * h;
                    int na = ng * 2 + h;
#pragma unroll
                    for (int ma = 0; ma < 2; ma++)
                        mma_f16(acc[ma][na], ah[ma], bhf);
                }
            }
        }
        __syncthreads();
    }

    // Epilogue: y[b][n][p]
    const int r = lane >> 2;
    const int cp = (lane & 3) * 2;
#pragma unroll
    for (int ma = 0; ma < 2; ma++) {
#pragma unroll
        for (int na = 0; na < 8; na++) {
#pragma unroll
            for (int v = 0; v < 4; v++) {
                int m = p0 + warp_m * 32 + ma * 16 + r + (v >> 1) * 8;
                int n = n0 + warp_n * 64 + na * 8 + cp + (v & 1);
                y[((size_t)(b * CCH + n)) * PIX + m] = acc[ma][na][v] + b2[n];
            }
        }
    }
}

// ---------------------------------------------------------------------------
extern "C" void kernel_launch(void* const* d_in, const int* in_sizes, int n_in,
                              void* d_out, int out_size) {
    const float* x  = (const float*)d_in[0];
    const float* W1 = (const float*)d_in[1];
    const float* b1 = (const float*)d_in[2];
    const float* W2 = (const float*)d_in[3];
    const float* b2 = (const float*)d_in[4];
    float* y = (float*)d_out;

    cudaFuncSetAttribute(attn_mma,
                         cudaFuncAttributeMaxDynamicSharedMemorySize, ATTN_SMEM);
    cudaFuncSetAttribute(qkv_mma,
                         cudaFuncAttributeMaxDynamicSharedMemorySize, GEMM_SMEM);
    cudaFuncSetAttribute(proj_mma,
                         cudaFuncAttributeMaxDynamicSharedMemorySize, GEMM_SMEM);

    __half *w1h, *w2h;
    cudaGetSymbolAddress((void**)&w1h, g_w1h);
    cudaGetSymbolAddress((void**)&w2h, g_w2h);

    // 0) fp32 -> fp16
    conv_x<<<dim3(PIX / 32, CCH / 32, BATCH), dim3(32, 8)>>>(x);
    conv_w<<<(768 * CCH + 255) / 256, 256>>>(W1, w1h, 768 * CCH);
    conv_w<<<(CCH * CCH + 255) / 256, 256>>>(W2, w2h, CCH * CCH);

    // 1) QKV: M=4096 (x128), N=768 (x128), per batch
    qkv_mma<<<dim3(PIX / 128, 768 / 128, BATCH), 256, GEMM_SMEM>>>(b1);

    // 2) Attention: (64 windows, 8 heads, 16 batches)
    attn_mma<<<dim3(NWIN * NWIN, NH, BATCH), 128, ATTN_SMEM>>>();

    // 3) Output projection: N=256 (x128)
    proj_mma<<<dim3(PIX / 128, CCH / 128, BATCH), 256, GEMM_SMEM>>>(b2, y);
}